// round 1
// baseline (speedup 1.0000x reference)
#include <cuda_runtime.h>

// ---------------------------------------------------------------------------
// Channel-attention module, algebraically factorized:
//   M[b]   = x[b] (CxN) @ q^T (NxC)                 (17.2 GF)
//   E[b]   = key_w @ M[b] + key_b (x) qsum          ( 2.1 GF)
//   att    = softmax_rows(E)
//   W2[b]  = att[b]^T @ value_w                     ( 2.1 GF)
//   bias2  = att[b]^T @ value_b
//   out[b] = gamma*(W2[b] @ x[b] + bias2) + x[b]    (17.2 GF, fused epilogue)
// All fp32 -> numerically equivalent to reference up to reassociation.
// ---------------------------------------------------------------------------

#define BATCH 8
#define CCH   512
#define NPIX  4096

__device__ float g_M [BATCH * CCH * CCH];
__device__ float g_E [BATCH * CCH * CCH];
__device__ float g_W2[BATCH * CCH * CCH];
__device__ float g_qsum[CCH];
__device__ float g_bias2[BATCH * CCH];

// ------------------------- generic tiled fp32 GEMM -------------------------
// C[m,n] = sum_k Aeff[m,k]*Beff[k,n], Aeff[m,k] = TA ? A[k*lda+m] : A[m*lda+k]
// EPI: 0 plain, 1 +e1[m]*e2[n], 2 gamma*(acc+e1[m]) + e2[m*ldc+n]
#define BM 128
#define BN 128
#define BK 16
#define TM 8
#define TN 8

template<bool TA, bool TB, int EPI>
__global__ __launch_bounds__(256, 2)
void gemm_kernel(const float* __restrict__ A, const float* __restrict__ B,
                 float* __restrict__ Cp,
                 int M, int N, int K, int lda, int ldb, int ldc,
                 long sA, long sB, long sC,
                 const float* __restrict__ e1, long se1,
                 const float* __restrict__ e2, long se2,
                 const float* __restrict__ gptr)
{
    __shared__ float As[BK][BM + 4];
    __shared__ float Bs[BK][BN + 4];

    const int bz = blockIdx.z;
    A  += (long)bz * sA;
    B  += (long)bz * sB;
    Cp += (long)bz * sC;
    const float* E1 = e1 ? e1 + (long)bz * se1 : (const float*)0;
    const float* E2 = e2 ? e2 + (long)bz * se2 : (const float*)0;

    const int m0  = blockIdx.y * BM;
    const int n0  = blockIdx.x * BN;
    const int tid = threadIdx.x;
    const int tx  = tid & 15;        // 0..15
    const int ty  = tid >> 4;        // 0..15
    const int row = ty * TM;         // tile-local row base
    const int col = tx * TN;         // tile-local col base

    float acc[TM][TN];
    #pragma unroll
    for (int i = 0; i < TM; i++)
        #pragma unroll
        for (int j = 0; j < TN; j++) acc[i][j] = 0.f;

    for (int k0 = 0; k0 < K; k0 += BK) {
        // ---- load A tile -> As[k][m] ----
        if (!TA) {
            #pragma unroll
            for (int it = 0; it < (BM * BK) / 256; it++) {
                int idx = it * 256 + tid;
                int m = idx / BK, k = idx % BK;
                As[k][m] = A[(long)(m0 + m) * lda + (k0 + k)];
            }
        } else {
            #pragma unroll
            for (int it = 0; it < (BM * BK) / 256; it++) {
                int idx = it * 256 + tid;
                int m = idx % BM, k = idx / BM;
                As[k][m] = A[(long)(k0 + k) * lda + (m0 + m)];
            }
        }
        // ---- load B tile -> Bs[k][n] ----
        if (!TB) {
            #pragma unroll
            for (int it = 0; it < (BN * BK) / 256; it++) {
                int idx = it * 256 + tid;
                int n = idx % BN, k = idx / BN;
                Bs[k][n] = B[(long)(k0 + k) * ldb + (n0 + n)];
            }
        } else {
            #pragma unroll
            for (int it = 0; it < (BN * BK) / 256; it++) {
                int idx = it * 256 + tid;
                int k = idx % BK, n = idx / BK;
                Bs[k][n] = B[(long)(n0 + n) * ldb + (k0 + k)];
            }
        }
        __syncthreads();

        #pragma unroll
        for (int k = 0; k < BK; k++) {
            float ar[TM], br[TN];
            #pragma unroll
            for (int i = 0; i < TM; i++) ar[i] = As[k][row + i];
            #pragma unroll
            for (int j = 0; j < TN; j++) br[j] = Bs[k][col + j];
            #pragma unroll
            for (int i = 0; i < TM; i++)
                #pragma unroll
                for (int j = 0; j < TN; j++)
                    acc[i][j] += ar[i] * br[j];
        }
        __syncthreads();
    }

    float g = 0.f;
    if (EPI == 2) g = gptr[0];

    #pragma unroll
    for (int i = 0; i < TM; i++) {
        int m = m0 + row + i;
        #pragma unroll
        for (int j = 0; j < TN; j++) {
            int n = n0 + col + j;
            float v = acc[i][j];
            if (EPI == 1) v += E1[m] * E2[n];
            if (EPI == 2) v = g * (v + E1[m]) + E2[(long)m * ldc + n];
            Cp[(long)m * ldc + n] = v;
        }
    }
}

// ------------------------- qsum[d] = sum_n q[d,n] --------------------------
__global__ void qsum_kernel(const float* __restrict__ q)
{
    int d = blockIdx.x;
    float s = 0.f;
    for (int n = threadIdx.x; n < NPIX; n += 256)
        s += q[(long)d * NPIX + n];
    #pragma unroll
    for (int o = 16; o; o >>= 1) s += __shfl_xor_sync(0xffffffffu, s, o);
    __shared__ float sh[8];
    if ((threadIdx.x & 31) == 0) sh[threadIdx.x >> 5] = s;
    __syncthreads();
    if (threadIdx.x == 0) {
        float t = 0.f;
        #pragma unroll
        for (int i = 0; i < 8; i++) t += sh[i];
        g_qsum[d] = t;
    }
}

// -------------------- softmax over last axis of E (rows of 512) ------------
__global__ void softmax_kernel()
{
    float* row = g_E + (long)blockIdx.x * CCH;
    int t = threadIdx.x;
    float v0 = row[t], v1 = row[t + 256];

    __shared__ float sh[8];
    float m = fmaxf(v0, v1);
    #pragma unroll
    for (int o = 16; o; o >>= 1) m = fmaxf(m, __shfl_xor_sync(0xffffffffu, m, o));
    if ((t & 31) == 0) sh[t >> 5] = m;
    __syncthreads();
    float mm = sh[0];
    #pragma unroll
    for (int i = 1; i < 8; i++) mm = fmaxf(mm, sh[i]);

    float e0 = expf(v0 - mm), e1 = expf(v1 - mm);
    float s = e0 + e1;
    #pragma unroll
    for (int o = 16; o; o >>= 1) s += __shfl_xor_sync(0xffffffffu, s, o);
    __syncthreads();                  // sh reuse
    if ((t & 31) == 0) sh[t >> 5] = s;
    __syncthreads();
    float ss = 0.f;
    #pragma unroll
    for (int i = 0; i < 8; i++) ss += sh[i];
    float inv = 1.f / ss;
    row[t]       = e0 * inv;
    row[t + 256] = e1 * inv;
}

// --------------- bias2[b,c] = sum_d att[b,d,c]*value_b[d] ------------------
__global__ void bias2_kernel(const float* __restrict__ vb)
{
    int idx = blockIdx.x * 256 + threadIdx.x;   // b*512 + c
    int b = idx >> 9, c = idx & 511;
    const float* att = g_E + (long)b * CCH * CCH;
    float s = 0.f;
    #pragma unroll 4
    for (int d = 0; d < CCH; d++)
        s += att[(long)d * CCH + c] * vb[d];
    g_bias2[idx] = s;
}

// ---------------------------------------------------------------------------
extern "C" void kernel_launch(void* const* d_in, const int* in_sizes, int n_in,
                              void* d_out, int out_size)
{
    const float* x     = (const float*)d_in[0];   // (8,512,64,64)
    const float* q     = (const float*)d_in[1];   // (512,64,64) -> (512,4096)
    const float* kw    = (const float*)d_in[2];   // (512,512)
    const float* kb    = (const float*)d_in[3];   // (512,)
    const float* vw    = (const float*)d_in[4];   // (512,512)
    const float* vb    = (const float*)d_in[5];   // (512,)
    const float* gamma = (const float*)d_in[6];   // (1,)
    float* out = (float*)d_out;

    float *pM, *pE, *pW2, *pq, *pb2;
    cudaGetSymbolAddress((void**)&pM,  g_M);
    cudaGetSymbolAddress((void**)&pE,  g_E);
    cudaGetSymbolAddress((void**)&pW2, g_W2);
    cudaGetSymbolAddress((void**)&pq,  g_qsum);
    cudaGetSymbolAddress((void**)&pb2, g_bias2);

    const long sBC = (long)CCH * CCH;      // 262144
    const long sBX = (long)CCH * NPIX;     // per-batch x stride

    // qsum
    qsum_kernel<<<CCH, 256>>>(q);

    // M[b] = x[b] @ q^T      (NT: A row-major MxK, B row-major NxK)
    gemm_kernel<false, true, 0><<<dim3(CCH / BN, CCH / BM, BATCH), 256>>>(
        x, q, pM, CCH, CCH, NPIX, NPIX, NPIX, CCH,
        sBX, 0, sBC, (const float*)0, 0, (const float*)0, 0, (const float*)0);

    // E[b] = key_w @ M[b] + key_b (x) qsum
    gemm_kernel<false, false, 1><<<dim3(CCH / BN, CCH / BM, BATCH), 256>>>(
        kw, pM, pE, CCH, CCH, CCH, CCH, CCH, CCH,
        0, sBC, sBC, kb, 0, pq, 0, (const float*)0);

    // att = softmax rows (in place in g_E)
    softmax_kernel<<<BATCH * CCH, 256>>>();

    // bias2
    bias2_kernel<<<(BATCH * CCH) / 256, 256>>>(vb);

    // W2[b] = att[b]^T @ value_w   (TN: A stored KxM)
    gemm_kernel<true, false, 0><<<dim3(CCH / BN, CCH / BM, BATCH), 256>>>(
        pE, vw, pW2, CCH, CCH, CCH, CCH, CCH, CCH,
        sBC, 0, sBC, (const float*)0, 0, (const float*)0, 0, (const float*)0);

    // out[b] = gamma*(W2[b] @ x[b] + bias2[b]) + x[b]
    gemm_kernel<false, false, 2><<<dim3(NPIX / BN, CCH / BM, BATCH), 256>>>(
        pW2, x, out, CCH, NPIX, CCH, CCH, NPIX, NPIX,
        sBC, sBX, sBX, pb2, CCH, x, sBX, gamma);
}

// round 4
// speedup vs baseline: 3.9050x; 3.9050x over previous
#include <cuda_runtime.h>
#include <cuda_bf16.h>
#include <stdint.h>

// ---------------------------------------------------------------------------
// Channel attention, factorized; GEMMs on classic tensor cores
// (mma.sync.m16n8k16 bf16 -> f32, hi/lo split: 3 MMAs per k-step).
//   P[b]  = q @ x[b]^T                       17.2 GF
//   E[b]  = kw . P[b] + kb (x) qsum           2.1 GF
//   att   = softmax rows(E)
//   W2[b] = attT . vwT                        2.1 GF
//   out   = gamma*(W2[b] @ xT + bias2) + x   17.2 GF
// All GEMMs: D[m][n] = sum_k A[m][k]*B[n][k]; A,B K-major bf16 hi/lo pairs.
// ---------------------------------------------------------------------------

#define BATCH 8
#define CCH   512
#define NPIX  4096

__device__ __nv_bfloat16 g_xh [BATCH*CCH*NPIX], g_xl [BATCH*CCH*NPIX];
__device__ __nv_bfloat16 g_xTh[BATCH*CCH*NPIX], g_xTl[BATCH*CCH*NPIX];
__device__ __nv_bfloat16 g_qh [CCH*NPIX],       g_ql [CCH*NPIX];
__device__ __nv_bfloat16 g_kwh[CCH*CCH],        g_kwl[CCH*CCH];
__device__ __nv_bfloat16 g_vwTh[CCH*CCH],       g_vwTl[CCH*CCH];
__device__ __nv_bfloat16 g_Ph [BATCH*CCH*CCH],  g_Pl [BATCH*CCH*CCH];
__device__ __nv_bfloat16 g_aTh[BATCH*CCH*CCH],  g_aTl[BATCH*CCH*CCH];
__device__ __nv_bfloat16 g_W2h[BATCH*CCH*CCH],  g_W2l[BATCH*CCH*CCH];
__device__ float g_E[BATCH*CCH*CCH];
__device__ float g_qsum[CCH];
__device__ float g_bias2[BATCH*CCH];

// --------------------------- asm helpers -----------------------------------
__device__ __forceinline__ uint32_t smem_u32(const void* p) {
    uint32_t a;
    asm("{ .reg .u64 t; cvta.to.shared.u64 t, %1; cvt.u32.u64 %0, t; }" : "=r"(a) : "l"(p));
    return a;
}
__device__ __forceinline__ void cp16(uint32_t saddr, const void* g) {
    asm volatile("cp.async.cg.shared.global [%0], [%1], 16;" :: "r"(saddr), "l"(g) : "memory");
}
__device__ __forceinline__ void cp_commit() {
    asm volatile("cp.async.commit_group;" ::: "memory");
}
template<int N>
__device__ __forceinline__ void cp_wait() {
    asm volatile("cp.async.wait_group %0;" :: "n"(N) : "memory");
}
__device__ __forceinline__ void ldsm4(uint32_t* r, uint32_t a) {
    asm volatile("ldmatrix.sync.aligned.m8n8.x4.shared.b16 {%0,%1,%2,%3}, [%4];"
                 : "=r"(r[0]), "=r"(r[1]), "=r"(r[2]), "=r"(r[3]) : "r"(a));
}
__device__ __forceinline__ void mma16816(float* d, const uint32_t* a, const uint32_t* b) {
    asm volatile("mma.sync.aligned.m16n8k16.row.col.f32.bf16.bf16.f32 "
                 "{%0,%1,%2,%3}, {%4,%5,%6,%7}, {%8,%9}, {%0,%1,%2,%3};"
                 : "+f"(d[0]), "+f"(d[1]), "+f"(d[2]), "+f"(d[3])
                 : "r"(a[0]), "r"(a[1]), "r"(a[2]), "r"(a[3]), "r"(b[0]), "r"(b[1]));
}

// --------------------------- GEMM kernel -----------------------------------
// CTA tile 128x128, BK=32. SMEM tiles 128 rows x 32 bf16, row padded to 80B.
// Per stage: Ah(10240) Al Bh Bl = 40960B; double buffered = 81920B.
#define RSB   80          // padded row stride, bytes
#define TILEB 10240       // one tile
#define STGB  40960       // one stage
#define GSMEM (2*STGB)

template<int EPI>
__global__ __launch_bounds__(256)
void gemm_bf16x3(const __nv_bfloat16* __restrict__ Ah, const __nv_bfloat16* __restrict__ Al,
                 const __nv_bfloat16* __restrict__ Bh, const __nv_bfloat16* __restrict__ Bl,
                 int ldA, int ldB, long sA, long sB, int K,
                 __nv_bfloat16* __restrict__ Dh, __nv_bfloat16* __restrict__ Dl,
                 float* __restrict__ Dout, int ldD, long sD,
                 const float* __restrict__ e1, long se1,
                 const float* __restrict__ e2,
                 const float* __restrict__ xres,
                 const float* __restrict__ gptr)
{
    extern __shared__ char sm[];
    const uint32_t sb = smem_u32(sm);
    const int tid = threadIdx.x, lane = tid & 31, wid = tid >> 5;
    const int wm = (wid >> 2) * 64, wn = (wid & 3) * 32;
    const int b  = blockIdx.z;
    const int m0 = blockIdx.y * 128, n0 = blockIdx.x * 128;

    Ah += b * sA;  Al += b * sA;
    Bh += b * sB;  Bl += b * sB;

    // per-lane ldmatrix offsets (bytes)
    const uint32_t aoff = ((lane & 7) + 8 * ((lane >> 3) & 1)) * RSB + (lane >> 4) * 16;
    const uint32_t boff = ((lane & 7) + 8 * (lane >> 4)) * RSB + ((lane >> 3) & 1) * 16;

    // per-thread load coords
    const int r0c = tid >> 2;            // row for chunk i=0 (0..63)
    const int c16 = tid & 3;             // 16B chunk in row

    float acc[4][4][4];
    #pragma unroll
    for (int i = 0; i < 4; i++)
        #pragma unroll
        for (int j = 0; j < 4; j++)
            #pragma unroll
            for (int v = 0; v < 4; v++) acc[i][j][v] = 0.f;

    const int nc = K >> 5;

    auto load_stage = [&](int stage, int k0) {
        uint32_t base = sb + stage * STGB;
        #pragma unroll
        for (int i = 0; i < 2; i++) {
            int row = r0c + i * 64;
            uint32_t so = base + row * RSB + c16 * 16;
            long gaoff = (long)(m0 + row) * ldA + k0 + c16 * 8;
            long gboff = (long)(n0 + row) * ldB + k0 + c16 * 8;
            cp16(so,             Ah + gaoff);
            cp16(so + TILEB,     Al + gaoff);
            cp16(so + 2 * TILEB, Bh + gboff);
            cp16(so + 3 * TILEB, Bl + gboff);
        }
    };

    auto compute_stage = [&](int stage) {
        uint32_t Abase = sb + stage * STGB;
        uint32_t Bbase = Abase + 2 * TILEB;
        #pragma unroll
        for (int ks = 0; ks < 2; ks++) {
            uint32_t kb2 = ks * 32;      // 16 halves = 32B
            uint32_t ah[4][4], al[4][4], bh[4][2], bl[4][2];
            #pragma unroll
            for (int mi = 0; mi < 4; mi++) {
                uint32_t ro = (wm + mi * 16) * RSB + kb2;
                ldsm4(ah[mi], Abase + ro + aoff);
                ldsm4(al[mi], Abase + TILEB + ro + aoff);
            }
            #pragma unroll
            for (int nb = 0; nb < 2; nb++) {
                uint32_t ro = (wn + nb * 16) * RSB + kb2;
                uint32_t t[4];
                ldsm4(t, Bbase + ro + boff);
                bh[2*nb][0] = t[0]; bh[2*nb][1] = t[1];
                bh[2*nb+1][0] = t[2]; bh[2*nb+1][1] = t[3];
                ldsm4(t, Bbase + TILEB + ro + boff);
                bl[2*nb][0] = t[0]; bl[2*nb][1] = t[1];
                bl[2*nb+1][0] = t[2]; bl[2*nb+1][1] = t[3];
            }
            #pragma unroll
            for (int mi = 0; mi < 4; mi++)
                #pragma unroll
                for (int ni = 0; ni < 4; ni++) {
                    mma16816(acc[mi][ni], ah[mi], bh[ni]);
                    mma16816(acc[mi][ni], ah[mi], bl[ni]);
                    mma16816(acc[mi][ni], al[mi], bh[ni]);
                }
        }
    };

    load_stage(0, 0);
    cp_commit();
    for (int c = 0; c < nc; c++) {
        if (c + 1 < nc) {
            load_stage((c + 1) & 1, (c + 1) * 32);
            cp_commit();
            cp_wait<1>();
        } else {
            cp_wait<0>();
        }
        __syncthreads();
        compute_stage(c & 1);
        __syncthreads();
    }

    // ------------------------------ epilogue -------------------------------
    float g = 0.f;
    if (EPI == 2) g = gptr[0];
    #pragma unroll
    for (int mi = 0; mi < 4; mi++) {
        #pragma unroll
        for (int half = 0; half < 2; half++) {
            int r = m0 + wm + mi * 16 + (lane >> 2) + half * 8;
            float e1r = 0.f;
            if (EPI == 1) e1r = e1[r];
            if (EPI == 2) e1r = e1[b * se1 + r];
            #pragma unroll
            for (int ni = 0; ni < 4; ni++) {
                int cidx = n0 + wn + ni * 8 + 2 * (lane & 3);
                float v0 = acc[mi][ni][half * 2 + 0];
                float v1 = acc[mi][ni][half * 2 + 1];
                long idx = (long)r * ldD + cidx;
                if (EPI == 0) {
                    __nv_bfloat16 h0 = __float2bfloat16(v0);
                    __nv_bfloat16 h1 = __float2bfloat16(v1);
                    __nv_bfloat162 ph; ph.x = h0; ph.y = h1;
                    __nv_bfloat162 pl;
                    pl.x = __float2bfloat16(v0 - __bfloat162float(h0));
                    pl.y = __float2bfloat16(v1 - __bfloat162float(h1));
                    *reinterpret_cast<__nv_bfloat162*>(Dh + b * sD + idx) = ph;
                    *reinterpret_cast<__nv_bfloat162*>(Dl + b * sD + idx) = pl;
                } else if (EPI == 1) {
                    float2 o;
                    o.x = v0 + e1r * e2[cidx];
                    o.y = v1 + e1r * e2[cidx + 1];
                    *reinterpret_cast<float2*>(Dout + b * sD + idx) = o;
                } else {
                    float2 xr = *reinterpret_cast<const float2*>(xres + b * sD + idx);
                    float2 o;
                    o.x = g * (v0 + e1r) + xr.x;
                    o.y = g * (v1 + e1r) + xr.y;
                    *reinterpret_cast<float2*>(Dout + b * sD + idx) = o;
                }
            }
        }
    }
}

// ------------------------- prep / small kernels ----------------------------
__global__ void cvt_pair(const float4* __restrict__ in, uint2* __restrict__ oh,
                         uint2* __restrict__ ol, int n4)
{
    int i = blockIdx.x * 256 + threadIdx.x;
    if (i >= n4) return;
    float4 v = in[i];
    float f[4] = {v.x, v.y, v.z, v.w};
    uint32_t hh[4], ll[4];
    #pragma unroll
    for (int j = 0; j < 4; j++) {
        __nv_bfloat16 h = __float2bfloat16(f[j]);
        __nv_bfloat16 l = __float2bfloat16(f[j] - __bfloat162float(h));
        hh[j] = __bfloat16_as_ushort(h);
        ll[j] = __bfloat16_as_ushort(l);
    }
    uint2 uh, ul;
    uh.x = hh[0] | (hh[1] << 16); uh.y = hh[2] | (hh[3] << 16);
    ul.x = ll[0] | (ll[1] << 16); ul.y = ll[2] | (ll[3] << 16);
    oh[i] = uh; ol[i] = ul;
}

__global__ void transpose_cvt(const float* __restrict__ in, __nv_bfloat16* __restrict__ oh,
                              __nv_bfloat16* __restrict__ ol, int ldin, int ldout,
                              long sIn, long sOut)
{
    __shared__ float t[32][33];
    long b = blockIdx.z;
    in += b * sIn; oh += b * sOut; ol += b * sOut;
    int x0 = blockIdx.x * 32, y0 = blockIdx.y * 32;
    int tx = threadIdx.x, ty = threadIdx.y;
    #pragma unroll
    for (int i = 0; i < 4; i++)
        t[ty + i * 8][tx] = in[(long)(y0 + ty + i * 8) * ldin + x0 + tx];
    __syncthreads();
    #pragma unroll
    for (int i = 0; i < 4; i++) {
        float v = t[tx][ty + i * 8];
        __nv_bfloat16 h = __float2bfloat16(v);
        long idx = (long)(x0 + ty + i * 8) * ldout + y0 + tx;
        oh[idx] = h;
        ol[idx] = __float2bfloat16(v - __bfloat162float(h));
    }
}

__global__ void qsum_kernel(const float* __restrict__ q)
{
    int d = blockIdx.x;
    float s = 0.f;
    for (int n = threadIdx.x; n < NPIX; n += 256)
        s += q[(long)d * NPIX + n];
    #pragma unroll
    for (int o = 16; o; o >>= 1) s += __shfl_xor_sync(0xffffffffu, s, o);
    __shared__ float sh[8];
    if ((threadIdx.x & 31) == 0) sh[threadIdx.x >> 5] = s;
    __syncthreads();
    if (threadIdx.x == 0) {
        float t = 0.f;
        #pragma unroll
        for (int i = 0; i < 8; i++) t += sh[i];
        g_qsum[d] = t;
    }
}

__global__ void softmax_kernel()
{
    float* row = g_E + (long)blockIdx.x * CCH;
    int t = threadIdx.x;
    float v0 = row[t], v1 = row[t + 256];
    __shared__ float sh[8];
    float m = fmaxf(v0, v1);
    #pragma unroll
    for (int o = 16; o; o >>= 1) m = fmaxf(m, __shfl_xor_sync(0xffffffffu, m, o));
    if ((t & 31) == 0) sh[t >> 5] = m;
    __syncthreads();
    float mm = sh[0];
    #pragma unroll
    for (int i = 1; i < 8; i++) mm = fmaxf(mm, sh[i]);
    float e0 = expf(v0 - mm), e1 = expf(v1 - mm);
    float s = e0 + e1;
    #pragma unroll
    for (int o = 16; o; o >>= 1) s += __shfl_xor_sync(0xffffffffu, s, o);
    __syncthreads();
    if ((t & 31) == 0) sh[t >> 5] = s;
    __syncthreads();
    float ss = 0.f;
    #pragma unroll
    for (int i = 0; i < 8; i++) ss += sh[i];
    float inv = 1.f / ss;
    row[t]       = e0 * inv;
    row[t + 256] = e1 * inv;
}

__global__ void bias2_kernel(const float* __restrict__ vb)
{
    int idx = blockIdx.x * 256 + threadIdx.x;
    int b = idx >> 9, c = idx & 511;
    const float* att = g_E + (long)b * CCH * CCH;
    float s = 0.f;
    #pragma unroll 4
    for (int d = 0; d < CCH; d++)
        s += att[(long)d * CCH + c] * vb[d];
    g_bias2[idx] = s;
}

// ---------------------------------------------------------------------------
extern "C" void kernel_launch(void* const* d_in, const int* in_sizes, int n_in,
                              void* d_out, int out_size)
{
    const float* x     = (const float*)d_in[0];
    const float* q     = (const float*)d_in[1];
    const float* kw    = (const float*)d_in[2];
    const float* kb    = (const float*)d_in[3];
    const float* vw    = (const float*)d_in[4];
    const float* vb    = (const float*)d_in[5];
    const float* gamma = (const float*)d_in[6];
    float* out = (float*)d_out;

    cudaFuncSetAttribute(gemm_bf16x3<0>, cudaFuncAttributeMaxDynamicSharedMemorySize, GSMEM);
    cudaFuncSetAttribute(gemm_bf16x3<1>, cudaFuncAttributeMaxDynamicSharedMemorySize, GSMEM);
    cudaFuncSetAttribute(gemm_bf16x3<2>, cudaFuncAttributeMaxDynamicSharedMemorySize, GSMEM);

    __nv_bfloat16 *xh, *xl, *xTh, *xTl, *qh, *ql, *kwh, *kwl, *vwTh, *vwTl;
    __nv_bfloat16 *Ph, *Pl, *aTh, *aTl, *W2h, *W2l;
    float *pE, *pq, *pb2;
    cudaGetSymbolAddress((void**)&xh,  g_xh);   cudaGetSymbolAddress((void**)&xl,  g_xl);
    cudaGetSymbolAddress((void**)&xTh, g_xTh);  cudaGetSymbolAddress((void**)&xTl, g_xTl);
    cudaGetSymbolAddress((void**)&qh,  g_qh);   cudaGetSymbolAddress((void**)&ql,  g_ql);
    cudaGetSymbolAddress((void**)&kwh, g_kwh);  cudaGetSymbolAddress((void**)&kwl, g_kwl);
    cudaGetSymbolAddress((void**)&vwTh,g_vwTh); cudaGetSymbolAddress((void**)&vwTl,g_vwTl);
    cudaGetSymbolAddress((void**)&Ph,  g_Ph);   cudaGetSymbolAddress((void**)&Pl,  g_Pl);
    cudaGetSymbolAddress((void**)&aTh, g_aTh);  cudaGetSymbolAddress((void**)&aTl, g_aTl);
    cudaGetSymbolAddress((void**)&W2h, g_W2h);  cudaGetSymbolAddress((void**)&W2l, g_W2l);
    cudaGetSymbolAddress((void**)&pE,  g_E);
    cudaGetSymbolAddress((void**)&pq,  g_qsum);
    cudaGetSymbolAddress((void**)&pb2, g_bias2);

    const long sCC = (long)CCH * CCH;
    const long sCN = (long)CCH * NPIX;

    // ---- prep ----
    qsum_kernel<<<CCH, 256>>>(q);
    cvt_pair<<<(BATCH*CCH*NPIX/4)/256, 256>>>((const float4*)x, (uint2*)xh, (uint2*)xl, BATCH*CCH*NPIX/4);
    cvt_pair<<<(CCH*NPIX/4)/256, 256>>>((const float4*)q, (uint2*)qh, (uint2*)ql, CCH*NPIX/4);
    cvt_pair<<<(CCH*CCH/4)/256, 256>>>((const float4*)kw, (uint2*)kwh, (uint2*)kwl, CCH*CCH/4);
    transpose_cvt<<<dim3(NPIX/32, CCH/32, BATCH), dim3(32,8)>>>(x, xTh, xTl, NPIX, CCH, sCN, sCN);
    transpose_cvt<<<dim3(CCH/32, CCH/32, 1), dim3(32,8)>>>(vw, vwTh, vwTl, CCH, CCH, 0, 0);

    // ---- GEMM1: P[b][d][c] = sum_n q[d][n]*x[b][c][n] ----
    gemm_bf16x3<0><<<dim3(4,4,BATCH), 256, GSMEM>>>(
        qh, ql, xh, xl, NPIX, NPIX, 0, sCN, NPIX,
        Ph, Pl, (float*)0, CCH, sCC,
        (const float*)0, 0, (const float*)0, (const float*)0, (const float*)0);

    // ---- GEMM2: E[b][c][d] = sum_k kw[c][k]*P[b][d][k] + kb[c]*qsum[d] ----
    gemm_bf16x3<1><<<dim3(4,4,BATCH), 256, GSMEM>>>(
        kwh, kwl, Ph, Pl, CCH, CCH, 0, sCC, CCH,
        (__nv_bfloat16*)0, (__nv_bfloat16*)0, pE, CCH, sCC,
        kb, 0, pq, (const float*)0, (const float*)0);

    // ---- softmax + bias2 + att transpose ----
    softmax_kernel<<<BATCH*CCH, 256>>>();
    bias2_kernel<<<(BATCH*CCH)/256, 256>>>(vb);
    transpose_cvt<<<dim3(CCH/32, CCH/32, BATCH), dim3(32,8)>>>(pE, aTh, aTl, CCH, CCH, sCC, sCC);

    // ---- GEMM3: W2[b][c][o] = sum_d attT[c][d]*vwT[o][d] ----
    gemm_bf16x3<0><<<dim3(4,4,BATCH), 256, GSMEM>>>(
        aTh, aTl, vwTh, vwTl, CCH, CCH, sCC, 0, CCH,
        W2h, W2l, (float*)0, CCH, sCC,
        (const float*)0, 0, (const float*)0, (const float*)0, (const float*)0);

    // ---- GEMM4: out[b][c][n] = gamma*(sum_o W2[c][o]*xT[n][o] + bias2[c]) + x ----
    gemm_bf16x3<2><<<dim3(NPIX/128, 4, BATCH), 256, GSMEM>>>(
        W2h, W2l, xTh, xTl, CCH, CCH, sCC, sCN, CCH,
        (__nv_bfloat16*)0, (__nv_bfloat16*)0, out, NPIX, sCN,
        pb2, CCH, (const float*)0, x, gamma);
}

// round 5
// speedup vs baseline: 4.9953x; 1.2792x over previous
#include <cuda_runtime.h>
#include <cuda_fp16.h>
#include <stdint.h>

// ---------------------------------------------------------------------------
// Channel attention, factorized; classic tensor cores mma.m16n8k16 fp16->f32.
//   P[b]  = q @ x[b]^T                 3-MMA split (hh+hl+lh), err ~2^-24
//   E[b]  = kw . P[b] + kb (x) qsum    3-MMA split
//   att   = softmax rows(E)
//   W2[b] = attT . vwT                 2-MMA (A single, B split)
//   out   = gamma*(W2 @ xT + b2) + x   2-MMA (A single, B split)
// ---------------------------------------------------------------------------

#define BATCH 8
#define CCH   512
#define NPIX  4096

__device__ __half g_xh [BATCH*CCH*NPIX], g_xl [BATCH*CCH*NPIX];
__device__ __half g_xTh[BATCH*CCH*NPIX], g_xTl[BATCH*CCH*NPIX];
__device__ __half g_qh [CCH*NPIX],       g_ql [CCH*NPIX];
__device__ __half g_kwh[CCH*CCH],        g_kwl[CCH*CCH];
__device__ __half g_vwTh[CCH*CCH],       g_vwTl[CCH*CCH];
__device__ __half g_Ph [BATCH*CCH*CCH],  g_Pl [BATCH*CCH*CCH];
__device__ __half g_aTh[BATCH*CCH*CCH];
__device__ __half g_W2h[BATCH*CCH*CCH];
__device__ float g_E[BATCH*CCH*CCH];
__device__ float g_qsum[CCH];
__device__ float g_bias2[BATCH*CCH];

// --------------------------- asm helpers -----------------------------------
__device__ __forceinline__ uint32_t smem_u32(const void* p) {
    uint32_t a;
    asm("{ .reg .u64 t; cvta.to.shared.u64 t, %1; cvt.u32.u64 %0, t; }" : "=r"(a) : "l"(p));
    return a;
}
__device__ __forceinline__ void cp16(uint32_t saddr, const void* g) {
    asm volatile("cp.async.cg.shared.global [%0], [%1], 16;" :: "r"(saddr), "l"(g) : "memory");
}
__device__ __forceinline__ void cp_commit() {
    asm volatile("cp.async.commit_group;" ::: "memory");
}
template<int N>
__device__ __forceinline__ void cp_wait() {
    asm volatile("cp.async.wait_group %0;" :: "n"(N) : "memory");
}
__device__ __forceinline__ void ldsm4(uint32_t* r, uint32_t a) {
    asm volatile("ldmatrix.sync.aligned.m8n8.x4.shared.b16 {%0,%1,%2,%3}, [%4];"
                 : "=r"(r[0]), "=r"(r[1]), "=r"(r[2]), "=r"(r[3]) : "r"(a));
}
__device__ __forceinline__ void mma16816(float* d, const uint32_t* a, const uint32_t* b) {
    asm volatile("mma.sync.aligned.m16n8k16.row.col.f32.f16.f16.f32 "
                 "{%0,%1,%2,%3}, {%4,%5,%6,%7}, {%8,%9}, {%0,%1,%2,%3};"
                 : "+f"(d[0]), "+f"(d[1]), "+f"(d[2]), "+f"(d[3])
                 : "r"(a[0]), "r"(a[1]), "r"(a[2]), "r"(a[3]), "r"(b[0]), "r"(b[1]));
}

// --------------------------- GEMM kernel -----------------------------------
// CTA tile 128x128, BK=32, 3-stage cp.async pipeline, 1 sync per chunk.
// SMEM tile: 128 rows x 32 halves, row padded to 80B. NMMA=3 -> 4 tiles/stage
// (Ah,Al,Bh,Bl); NMMA=2 -> 3 tiles (Ah,Bh,Bl).
#define RSB   80
#define TILEB 10240

// EPI: 0 = half hi/lo pair out; 1 = f32 + e1[m]*e2[n]; 2 = gamma*(v+e1)+xres;
//      3 = half hi only.
template<int NMMA, int EPI>
__global__ __launch_bounds__(256)
void gemm_f16(const __half* __restrict__ Ah, const __half* __restrict__ Al,
              const __half* __restrict__ Bh, const __half* __restrict__ Bl,
              int ldA, int ldB, long sA, long sB, int K,
              __half* __restrict__ Dh, __half* __restrict__ Dl,
              float* __restrict__ Dout, int ldD, long sD,
              const float* __restrict__ e1, long se1,
              const float* __restrict__ e2,
              const float* __restrict__ xres,
              const float* __restrict__ gptr)
{
    constexpr int NTILES = (NMMA == 3) ? 4 : 3;
    constexpr int STGB   = NTILES * TILEB;
    constexpr int BOFF   = (NMMA == 3) ? 2 * TILEB : TILEB;

    extern __shared__ char sm[];
    const uint32_t sb = smem_u32(sm);
    const int tid = threadIdx.x, lane = tid & 31, wid = tid >> 5;
    const int wm = (wid >> 2) * 64, wn = (wid & 3) * 32;
    const int b  = blockIdx.z;
    const int m0 = blockIdx.y * 128, n0 = blockIdx.x * 128;

    Ah += b * sA;  if (NMMA == 3) Al += b * sA;
    Bh += b * sB;  Bl += b * sB;

    const uint32_t aoff = ((lane & 7) + 8 * ((lane >> 3) & 1)) * RSB + (lane >> 4) * 16;
    const uint32_t boff = ((lane & 7) + 8 * (lane >> 4)) * RSB + ((lane >> 3) & 1) * 16;

    const int r0c = tid >> 2;
    const int c16 = tid & 3;

    float acc[4][4][4];
    #pragma unroll
    for (int i = 0; i < 4; i++)
        #pragma unroll
        for (int j = 0; j < 4; j++)
            #pragma unroll
            for (int v = 0; v < 4; v++) acc[i][j][v] = 0.f;

    const int nc = K >> 5;

    auto load_stage = [&](int stage, int k0) {
        uint32_t base = sb + stage * STGB;
        #pragma unroll
        for (int i = 0; i < 2; i++) {
            int row = r0c + i * 64;
            uint32_t so = base + row * RSB + c16 * 16;
            long ga = (long)(m0 + row) * ldA + k0 + c16 * 8;
            long gb = (long)(n0 + row) * ldB + k0 + c16 * 8;
            cp16(so, Ah + ga);
            if (NMMA == 3) cp16(so + TILEB, Al + ga);
            cp16(so + BOFF,         Bh + gb);
            cp16(so + BOFF + TILEB, Bl + gb);
        }
    };

    auto compute_stage = [&](int stage) {
        uint32_t Abase = sb + stage * STGB;
        uint32_t Bbase = Abase + BOFF;
        #pragma unroll
        for (int ks = 0; ks < 2; ks++) {
            uint32_t kb2 = ks * 32;
            uint32_t ah[4][4], al[4][4], bh[4][2], bl[4][2];
            #pragma unroll
            for (int mi = 0; mi < 4; mi++) {
                uint32_t ro = (wm + mi * 16) * RSB + kb2;
                ldsm4(ah[mi], Abase + ro + aoff);
                if (NMMA == 3) ldsm4(al[mi], Abase + TILEB + ro + aoff);
            }
            #pragma unroll
            for (int nb = 0; nb < 2; nb++) {
                uint32_t ro = (wn + nb * 16) * RSB + kb2;
                uint32_t t[4];
                ldsm4(t, Bbase + ro + boff);
                bh[2*nb][0] = t[0]; bh[2*nb][1] = t[1];
                bh[2*nb+1][0] = t[2]; bh[2*nb+1][1] = t[3];
                ldsm4(t, Bbase + TILEB + ro + boff);
                bl[2*nb][0] = t[0]; bl[2*nb][1] = t[1];
                bl[2*nb+1][0] = t[2]; bl[2*nb+1][1] = t[3];
            }
            #pragma unroll
            for (int mi = 0; mi < 4; mi++)
                #pragma unroll
                for (int ni = 0; ni < 4; ni++) {
                    mma16816(acc[mi][ni], ah[mi], bh[ni]);
                    mma16816(acc[mi][ni], ah[mi], bl[ni]);
                    if (NMMA == 3) mma16816(acc[mi][ni], al[mi], bh[ni]);
                }
        }
    };

    // 3-stage pipeline
    load_stage(0, 0);
    cp_commit();
    if (nc > 1) load_stage(1, 32);
    cp_commit();
    for (int c = 0; c < nc; c++) {
        cp_wait<1>();
        __syncthreads();
        if (c + 2 < nc) load_stage((c + 2) % 3, (c + 2) * 32);
        cp_commit();
        compute_stage(c % 3);
    }

    // ------------------------------ epilogue -------------------------------
    float g = 0.f;
    if (EPI == 2) g = gptr[0];
    #pragma unroll
    for (int mi = 0; mi < 4; mi++) {
        #pragma unroll
        for (int half_ = 0; half_ < 2; half_++) {
            int r = m0 + wm + mi * 16 + (lane >> 2) + half_ * 8;
            float e1r = 0.f;
            if (EPI == 1) e1r = e1[r];
            if (EPI == 2) e1r = e1[b * se1 + r];
            #pragma unroll
            for (int ni = 0; ni < 4; ni++) {
                int cidx = n0 + wn + ni * 8 + 2 * (lane & 3);
                float v0 = acc[mi][ni][half_ * 2 + 0];
                float v1 = acc[mi][ni][half_ * 2 + 1];
                long idx = (long)r * ldD + cidx;
                if (EPI == 0) {
                    __half h0 = __float2half_rn(v0), h1 = __float2half_rn(v1);
                    __half2 ph; ph.x = h0; ph.y = h1;
                    __half2 pl;
                    pl.x = __float2half_rn(v0 - __half2float(h0));
                    pl.y = __float2half_rn(v1 - __half2float(h1));
                    *reinterpret_cast<__half2*>(Dh + b * sD + idx) = ph;
                    *reinterpret_cast<__half2*>(Dl + b * sD + idx) = pl;
                } else if (EPI == 3) {
                    __half2 ph;
                    ph.x = __float2half_rn(v0); ph.y = __float2half_rn(v1);
                    *reinterpret_cast<__half2*>(Dh + b * sD + idx) = ph;
                } else if (EPI == 1) {
                    float2 o;
                    o.x = v0 + e1r * e2[cidx];
                    o.y = v1 + e1r * e2[cidx + 1];
                    *reinterpret_cast<float2*>(Dout + b * sD + idx) = o;
                } else {
                    float2 xr = *reinterpret_cast<const float2*>(xres + b * sD + idx);
                    float2 o;
                    o.x = g * (v0 + e1r) + xr.x;
                    o.y = g * (v1 + e1r) + xr.y;
                    *reinterpret_cast<float2*>(Dout + b * sD + idx) = o;
                }
            }
        }
    }
}

// ------------------------- prep kernels ------------------------------------
__device__ __forceinline__ void split_h(float f, __half& h, __half& l) {
    h = __float2half_rn(f);
    l = __float2half_rn(f - __half2float(h));
}

// fused convert + transpose for x: writes xh/xl (CxN) and xTh/xTl (NxC)
__global__ void xprep_kernel(const float* __restrict__ x,
                             __half* __restrict__ xh, __half* __restrict__ xl,
                             __half* __restrict__ xTh, __half* __restrict__ xTl)
{
    __shared__ float t[32][33];
    long b = blockIdx.z;
    const float* xb = x + b * (long)CCH * NPIX;
    int n0 = blockIdx.x * 32, c0 = blockIdx.y * 32;
    int tx = threadIdx.x, ty = threadIdx.y;
    #pragma unroll
    for (int i = 0; i < 4; i++)
        t[ty + i * 8][tx] = xb[(long)(c0 + ty + i * 8) * NPIX + n0 + tx];
    __syncthreads();
    long sb_ = b * (long)CCH * NPIX;
    #pragma unroll
    for (int i = 0; i < 4; i++) {
        // straight
        float f = t[ty + i * 8][tx];
        __half h, l; split_h(f, h, l);
        long idx = sb_ + (long)(c0 + ty + i * 8) * NPIX + n0 + tx;
        xh[idx] = h; xl[idx] = l;
        // transposed
        float ft = t[tx][ty + i * 8];
        __half ht, lt; split_h(ft, ht, lt);
        long idxT = sb_ + (long)(n0 + ty + i * 8) * CCH + c0 + tx;
        xTh[idxT] = ht; xTl[idxT] = lt;
    }
}

__global__ void cvt_pair_h(const float4* __restrict__ in, uint2* __restrict__ oh,
                           uint2* __restrict__ ol, int n4)
{
    int i = blockIdx.x * 256 + threadIdx.x;
    if (i >= n4) return;
    float4 v = in[i];
    float f[4] = {v.x, v.y, v.z, v.w};
    uint16_t hh[4], ll[4];
    #pragma unroll
    for (int j = 0; j < 4; j++) {
        __half h, l; split_h(f[j], h, l);
        hh[j] = __half_as_ushort(h);
        ll[j] = __half_as_ushort(l);
    }
    uint2 uh, ul;
    uh.x = hh[0] | ((uint32_t)hh[1] << 16); uh.y = hh[2] | ((uint32_t)hh[3] << 16);
    ul.x = ll[0] | ((uint32_t)ll[1] << 16); ul.y = ll[2] | ((uint32_t)ll[3] << 16);
    oh[i] = uh; ol[i] = ul;
}

// transpose fp32 -> half hi (+ optional lo)
__global__ void transpose_cvt_h(const float* __restrict__ in, __half* __restrict__ oh,
                                __half* __restrict__ ol, int ldin, int ldout,
                                long sIn, long sOut)
{
    __shared__ float t[32][33];
    long b = blockIdx.z;
    in += b * sIn; oh += b * sOut;
    if (ol) ol += b * sOut;
    int x0 = blockIdx.x * 32, y0 = blockIdx.y * 32;
    int tx = threadIdx.x, ty = threadIdx.y;
    #pragma unroll
    for (int i = 0; i < 4; i++)
        t[ty + i * 8][tx] = in[(long)(y0 + ty + i * 8) * ldin + x0 + tx];
    __syncthreads();
    #pragma unroll
    for (int i = 0; i < 4; i++) {
        float v = t[tx][ty + i * 8];
        __half h = __float2half_rn(v);
        long idx = (long)(x0 + ty + i * 8) * ldout + y0 + tx;
        oh[idx] = h;
        if (ol) ol[idx] = __float2half_rn(v - __half2float(h));
    }
}

__global__ void qsum_kernel(const float* __restrict__ q)
{
    int d = blockIdx.x;
    float s = 0.f;
    for (int n = threadIdx.x; n < NPIX; n += 256)
        s += q[(long)d * NPIX + n];
    #pragma unroll
    for (int o = 16; o; o >>= 1) s += __shfl_xor_sync(0xffffffffu, s, o);
    __shared__ float sh[8];
    if ((threadIdx.x & 31) == 0) sh[threadIdx.x >> 5] = s;
    __syncthreads();
    if (threadIdx.x == 0) {
        float t = 0.f;
        #pragma unroll
        for (int i = 0; i < 8; i++) t += sh[i];
        g_qsum[d] = t;
    }
}

__global__ void softmax_kernel()
{
    float* row = g_E + (long)blockIdx.x * CCH;
    int t = threadIdx.x;
    float v0 = row[t], v1 = row[t + 256];
    __shared__ float sh[8];
    float m = fmaxf(v0, v1);
    #pragma unroll
    for (int o = 16; o; o >>= 1) m = fmaxf(m, __shfl_xor_sync(0xffffffffu, m, o));
    if ((t & 31) == 0) sh[t >> 5] = m;
    __syncthreads();
    float mm = sh[0];
    #pragma unroll
    for (int i = 1; i < 8; i++) mm = fmaxf(mm, sh[i]);
    float e0 = expf(v0 - mm), e1 = expf(v1 - mm);
    float s = e0 + e1;
    #pragma unroll
    for (int o = 16; o; o >>= 1) s += __shfl_xor_sync(0xffffffffu, s, o);
    __syncthreads();
    if ((t & 31) == 0) sh[t >> 5] = s;
    __syncthreads();
    float ss = 0.f;
    #pragma unroll
    for (int i = 0; i < 8; i++) ss += sh[i];
    float inv = 1.f / ss;
    row[t]       = e0 * inv;
    row[t + 256] = e1 * inv;
}

__global__ void bias2_kernel(const float* __restrict__ vb)
{
    int idx = blockIdx.x * 256 + threadIdx.x;
    int b = idx >> 9, c = idx & 511;
    const float* att = g_E + (long)b * CCH * CCH;
    float s = 0.f;
    #pragma unroll 4
    for (int d = 0; d < CCH; d++)
        s += att[(long)d * CCH + c] * vb[d];
    g_bias2[idx] = s;
}

// ---------------------------------------------------------------------------
extern "C" void kernel_launch(void* const* d_in, const int* in_sizes, int n_in,
                              void* d_out, int out_size)
{
    const float* x     = (const float*)d_in[0];
    const float* q     = (const float*)d_in[1];
    const float* kw    = (const float*)d_in[2];
    const float* kb    = (const float*)d_in[3];
    const float* vw    = (const float*)d_in[4];
    const float* vb    = (const float*)d_in[5];
    const float* gamma = (const float*)d_in[6];
    float* out = (float*)d_out;

    const int SM3 = 3 * 4 * TILEB;   // 122880
    const int SM2 = 3 * 3 * TILEB;   // 92160
    cudaFuncSetAttribute(gemm_f16<3,0>, cudaFuncAttributeMaxDynamicSharedMemorySize, SM3);
    cudaFuncSetAttribute(gemm_f16<3,1>, cudaFuncAttributeMaxDynamicSharedMemorySize, SM3);
    cudaFuncSetAttribute(gemm_f16<2,3>, cudaFuncAttributeMaxDynamicSharedMemorySize, SM2);
    cudaFuncSetAttribute(gemm_f16<2,2>, cudaFuncAttributeMaxDynamicSharedMemorySize, SM2);

    __half *xh, *xl, *xTh, *xTl, *qh, *ql, *kwh, *kwl, *vwTh, *vwTl;
    __half *Ph, *Pl, *aTh, *W2h;
    float *pE, *pq, *pb2;
    cudaGetSymbolAddress((void**)&xh,  g_xh);   cudaGetSymbolAddress((void**)&xl,  g_xl);
    cudaGetSymbolAddress((void**)&xTh, g_xTh);  cudaGetSymbolAddress((void**)&xTl, g_xTl);
    cudaGetSymbolAddress((void**)&qh,  g_qh);   cudaGetSymbolAddress((void**)&ql,  g_ql);
    cudaGetSymbolAddress((void**)&kwh, g_kwh);  cudaGetSymbolAddress((void**)&kwl, g_kwl);
    cudaGetSymbolAddress((void**)&vwTh,g_vwTh); cudaGetSymbolAddress((void**)&vwTl,g_vwTl);
    cudaGetSymbolAddress((void**)&Ph,  g_Ph);   cudaGetSymbolAddress((void**)&Pl,  g_Pl);
    cudaGetSymbolAddress((void**)&aTh, g_aTh);  cudaGetSymbolAddress((void**)&W2h, g_W2h);
    cudaGetSymbolAddress((void**)&pE,  g_E);
    cudaGetSymbolAddress((void**)&pq,  g_qsum);
    cudaGetSymbolAddress((void**)&pb2, g_bias2);

    const long sCC = (long)CCH * CCH;
    const long sCN = (long)CCH * NPIX;

    // ---- prep ----
    qsum_kernel<<<CCH, 256>>>(q);
    xprep_kernel<<<dim3(NPIX/32, CCH/32, BATCH), dim3(32,8)>>>(x, xh, xl, xTh, xTl);
    cvt_pair_h<<<(CCH*NPIX/4)/256, 256>>>((const float4*)q, (uint2*)qh, (uint2*)ql, CCH*NPIX/4);
    cvt_pair_h<<<(CCH*CCH/4)/256, 256>>>((const float4*)kw, (uint2*)kwh, (uint2*)kwl, CCH*CCH/4);
    transpose_cvt_h<<<dim3(CCH/32, CCH/32, 1), dim3(32,8)>>>(vw, vwTh, vwTl, CCH, CCH, 0, 0);

    // ---- GEMM1: P[b][d][c] = sum_n q[d][n]*x[b][c][n]  (3-MMA) ----
    gemm_f16<3,0><<<dim3(4,4,BATCH), 256, SM3>>>(
        qh, ql, xh, xl, NPIX, NPIX, 0, sCN, NPIX,
        Ph, Pl, (float*)0, CCH, sCC,
        (const float*)0, 0, (const float*)0, (const float*)0, (const float*)0);

    // ---- GEMM2: E[b][c][d] = sum_k kw[c][k]*P[b][d][k] + kb[c]*qsum[d] (3-MMA) ----
    gemm_f16<3,1><<<dim3(4,4,BATCH), 256, SM3>>>(
        kwh, kwl, Ph, Pl, CCH, CCH, 0, sCC, CCH,
        (__half*)0, (__half*)0, pE, CCH, sCC,
        kb, 0, pq, (const float*)0, (const float*)0);

    // ---- softmax + bias2 + att transpose (hi only) ----
    softmax_kernel<<<BATCH*CCH, 256>>>();
    bias2_kernel<<<(BATCH*CCH)/256, 256>>>(vb);
    transpose_cvt_h<<<dim3(CCH/32, CCH/32, BATCH), dim3(32,8)>>>(pE, aTh, (__half*)0, CCH, CCH, sCC, sCC);

    // ---- GEMM3: W2[b][c][o] = sum_d attT[c][d]*vwT[o][d]  (2-MMA) ----
    gemm_f16<2,3><<<dim3(4,4,BATCH), 256, SM2>>>(
        aTh, (__half*)0, vwTh, vwTl, CCH, CCH, sCC, 0, CCH,
        W2h, (__half*)0, (float*)0, CCH, sCC,
        (const float*)0, 0, (const float*)0, (const float*)0, (const float*)0);

    // ---- GEMM4: out = gamma*(W2 @ xT + bias2) + x  (2-MMA) ----
    gemm_f16<2,2><<<dim3(NPIX/128, 4, BATCH), 256, SM2>>>(
        W2h, (__half*)0, xTh, xTl, CCH, CCH, sCC, sCN, CCH,
        (__half*)0, (__half*)0, out, NPIX, sCN,
        pb2, CCH, (const float*)0, x, gamma);
}

// round 6
// speedup vs baseline: 5.6151x; 1.1241x over previous
#include <cuda_runtime.h>
#include <cuda_fp16.h>
#include <stdint.h>

// ---------------------------------------------------------------------------
// Channel attention, factorized; classic tensor cores mma.m16n8k16 fp16->f32.
//   P[b]  = q @ x[b]^T                 3-MMA split (hh+hl+lh)  [pre-softmax]
//   E[b]  = kw . P[b] + kb (x) qsum    3-MMA split             [pre-softmax]
//   att   = softmax rows(E)
//   W2[b] = attT . vwT                 1-MMA plain fp16
//   out   = gamma*(W2 @ xT + b2) + x   1-MMA plain fp16
// ---------------------------------------------------------------------------

#define BATCH 8
#define CCH   512
#define NPIX  4096

__device__ __half g_xh [BATCH*CCH*NPIX], g_xl [BATCH*CCH*NPIX];
__device__ __half g_xTh[BATCH*CCH*NPIX];
__device__ __half g_qh [CCH*NPIX],       g_ql [CCH*NPIX];
__device__ __half g_kwh[CCH*CCH],        g_kwl[CCH*CCH];
__device__ __half g_vwTh[CCH*CCH];
__device__ __half g_Ph [BATCH*CCH*CCH],  g_Pl [BATCH*CCH*CCH];
__device__ __half g_aTh[BATCH*CCH*CCH];
__device__ __half g_W2h[BATCH*CCH*CCH];
__device__ float g_E[BATCH*CCH*CCH];
__device__ float g_qsum[CCH];
__device__ float g_bias2[BATCH*CCH];

// --------------------------- asm helpers -----------------------------------
__device__ __forceinline__ uint32_t smem_u32(const void* p) {
    uint32_t a;
    asm("{ .reg .u64 t; cvta.to.shared.u64 t, %1; cvt.u32.u64 %0, t; }" : "=r"(a) : "l"(p));
    return a;
}
__device__ __forceinline__ void cp16(uint32_t saddr, const void* g) {
    asm volatile("cp.async.cg.shared.global [%0], [%1], 16;" :: "r"(saddr), "l"(g) : "memory");
}
__device__ __forceinline__ void cp_commit() {
    asm volatile("cp.async.commit_group;" ::: "memory");
}
template<int N>
__device__ __forceinline__ void cp_wait() {
    asm volatile("cp.async.wait_group %0;" :: "n"(N) : "memory");
}
__device__ __forceinline__ void ldsm4(uint32_t* r, uint32_t a) {
    asm volatile("ldmatrix.sync.aligned.m8n8.x4.shared.b16 {%0,%1,%2,%3}, [%4];"
                 : "=r"(r[0]), "=r"(r[1]), "=r"(r[2]), "=r"(r[3]) : "r"(a));
}
__device__ __forceinline__ void mma16816(float* d, const uint32_t* a, const uint32_t* b) {
    asm volatile("mma.sync.aligned.m16n8k16.row.col.f32.f16.f16.f32 "
                 "{%0,%1,%2,%3}, {%4,%5,%6,%7}, {%8,%9}, {%0,%1,%2,%3};"
                 : "+f"(d[0]), "+f"(d[1]), "+f"(d[2]), "+f"(d[3])
                 : "r"(a[0]), "r"(a[1]), "r"(a[2]), "r"(a[3]), "r"(b[0]), "r"(b[1]));
}

// --------------------------- GEMM kernel -----------------------------------
// CTA tile 128x128, BK=32, 3-stage cp.async pipeline, 1 sync per chunk.
// SMEM tile: 128 rows x 32 halves, row padded to 80B.
// NMMA=3: tiles Ah,Al,Bh,Bl.  NMMA=2: Ah,Bh,Bl.  NMMA=1: Ah,Bh.
#define RSB   80
#define TILEB 10240

// EPI: 0 = half hi/lo pair out; 1 = f32 + e1[m]*e2[n]; 2 = gamma*(v+e1)+xres;
//      3 = half hi only.
template<int NMMA, int EPI>
__global__ __launch_bounds__(256)
void gemm_f16(const __half* __restrict__ Ah, const __half* __restrict__ Al,
              const __half* __restrict__ Bh, const __half* __restrict__ Bl,
              int ldA, int ldB, long sA, long sB, int K,
              __half* __restrict__ Dh, __half* __restrict__ Dl,
              float* __restrict__ Dout, int ldD, long sD,
              const float* __restrict__ e1, long se1,
              const float* __restrict__ e2,
              const float* __restrict__ xres,
              const float* __restrict__ gptr)
{
    constexpr int NTILES = (NMMA == 3) ? 4 : (NMMA == 2) ? 3 : 2;
    constexpr int STGB   = NTILES * TILEB;
    constexpr int BOFF   = (NMMA == 3) ? 2 * TILEB : TILEB;

    extern __shared__ char sm[];
    const uint32_t sb = smem_u32(sm);
    const int tid = threadIdx.x, lane = tid & 31, wid = tid >> 5;
    const int wm = (wid >> 2) * 64, wn = (wid & 3) * 32;
    const int b  = blockIdx.z;
    const int m0 = blockIdx.y * 128, n0 = blockIdx.x * 128;

    Ah += b * sA;  if (NMMA == 3) Al += b * sA;
    Bh += b * sB;  if (NMMA >= 2) Bl += b * sB;

    const uint32_t aoff = ((lane & 7) + 8 * ((lane >> 3) & 1)) * RSB + (lane >> 4) * 16;
    const uint32_t boff = ((lane & 7) + 8 * (lane >> 4)) * RSB + ((lane >> 3) & 1) * 16;

    const int r0c = tid >> 2;
    const int c16 = tid & 3;

    float acc[4][4][4];
    #pragma unroll
    for (int i = 0; i < 4; i++)
        #pragma unroll
        for (int j = 0; j < 4; j++)
            #pragma unroll
            for (int v = 0; v < 4; v++) acc[i][j][v] = 0.f;

    const int nc = K >> 5;

    auto load_stage = [&](int stage, int k0) {
        uint32_t base = sb + stage * STGB;
        #pragma unroll
        for (int i = 0; i < 2; i++) {
            int row = r0c + i * 64;
            uint32_t so = base + row * RSB + c16 * 16;
            long ga = (long)(m0 + row) * ldA + k0 + c16 * 8;
            long gb = (long)(n0 + row) * ldB + k0 + c16 * 8;
            cp16(so, Ah + ga);
            if (NMMA == 3) cp16(so + TILEB, Al + ga);
            cp16(so + BOFF, Bh + gb);
            if (NMMA >= 2) cp16(so + BOFF + TILEB, Bl + gb);
        }
    };

    auto compute_stage = [&](int stage) {
        uint32_t Abase = sb + stage * STGB;
        uint32_t Bbase = Abase + BOFF;
        #pragma unroll
        for (int ks = 0; ks < 2; ks++) {
            uint32_t kb2 = ks * 32;
            uint32_t ah[4][4], al[4][4], bh[4][2], bl[4][2];
            #pragma unroll
            for (int mi = 0; mi < 4; mi++) {
                uint32_t ro = (wm + mi * 16) * RSB + kb2;
                ldsm4(ah[mi], Abase + ro + aoff);
                if (NMMA == 3) ldsm4(al[mi], Abase + TILEB + ro + aoff);
            }
            #pragma unroll
            for (int nb = 0; nb < 2; nb++) {
                uint32_t ro = (wn + nb * 16) * RSB + kb2;
                uint32_t t[4];
                ldsm4(t, Bbase + ro + boff);
                bh[2*nb][0] = t[0]; bh[2*nb][1] = t[1];
                bh[2*nb+1][0] = t[2]; bh[2*nb+1][1] = t[3];
                if (NMMA >= 2) {
                    ldsm4(t, Bbase + TILEB + ro + boff);
                    bl[2*nb][0] = t[0]; bl[2*nb][1] = t[1];
                    bl[2*nb+1][0] = t[2]; bl[2*nb+1][1] = t[3];
                }
            }
            #pragma unroll
            for (int mi = 0; mi < 4; mi++)
                #pragma unroll
                for (int ni = 0; ni < 4; ni++) {
                    mma16816(acc[mi][ni], ah[mi], bh[ni]);
                    if (NMMA >= 2) mma16816(acc[mi][ni], ah[mi], bl[ni]);
                    if (NMMA == 3) mma16816(acc[mi][ni], al[mi], bh[ni]);
                }
        }
    };

    // 3-stage pipeline
    load_stage(0, 0);
    cp_commit();
    if (nc > 1) load_stage(1, 32);
    cp_commit();
    for (int c = 0; c < nc; c++) {
        cp_wait<1>();
        __syncthreads();
        if (c + 2 < nc) load_stage((c + 2) % 3, (c + 2) * 32);
        cp_commit();
        compute_stage(c % 3);
    }

    // ------------------------------ epilogue -------------------------------
    float g = 0.f;
    if (EPI == 2) g = gptr[0];
    #pragma unroll
    for (int mi = 0; mi < 4; mi++) {
        #pragma unroll
        for (int half_ = 0; half_ < 2; half_++) {
            int r = m0 + wm + mi * 16 + (lane >> 2) + half_ * 8;
            float e1r = 0.f;
            if (EPI == 1) e1r = e1[r];
            if (EPI == 2) e1r = e1[b * se1 + r];
            #pragma unroll
            for (int ni = 0; ni < 4; ni++) {
                int cidx = n0 + wn + ni * 8 + 2 * (lane & 3);
                float v0 = acc[mi][ni][half_ * 2 + 0];
                float v1 = acc[mi][ni][half_ * 2 + 1];
                long idx = (long)r * ldD + cidx;
                if (EPI == 0) {
                    __half h0 = __float2half_rn(v0), h1 = __float2half_rn(v1);
                    __half2 ph; ph.x = h0; ph.y = h1;
                    __half2 pl;
                    pl.x = __float2half_rn(v0 - __half2float(h0));
                    pl.y = __float2half_rn(v1 - __half2float(h1));
                    *reinterpret_cast<__half2*>(Dh + b * sD + idx) = ph;
                    *reinterpret_cast<__half2*>(Dl + b * sD + idx) = pl;
                } else if (EPI == 3) {
                    __half2 ph;
                    ph.x = __float2half_rn(v0); ph.y = __float2half_rn(v1);
                    *reinterpret_cast<__half2*>(Dh + b * sD + idx) = ph;
                } else if (EPI == 1) {
                    float2 o;
                    o.x = v0 + e1r * e2[cidx];
                    o.y = v1 + e1r * e2[cidx + 1];
                    *reinterpret_cast<float2*>(Dout + b * sD + idx) = o;
                } else {
                    float2 xr = *reinterpret_cast<const float2*>(xres + b * sD + idx);
                    float2 o;
                    o.x = g * (v0 + e1r) + xr.x;
                    o.y = g * (v1 + e1r) + xr.y;
                    *reinterpret_cast<float2*>(Dout + b * sD + idx) = o;
                }
            }
        }
    }
}

// ------------------------- prep kernels ------------------------------------
__device__ __forceinline__ void split_h(float f, __half& h, __half& l) {
    h = __float2half_rn(f);
    l = __float2half_rn(f - __half2float(h));
}

// fused convert + transpose for x: writes xh/xl (CxN) and xTh (NxC, hi only)
__global__ void xprep_kernel(const float* __restrict__ x,
                             __half* __restrict__ xh, __half* __restrict__ xl,
                             __half* __restrict__ xTh)
{
    __shared__ float t[32][33];
    long b = blockIdx.z;
    const float* xb = x + b * (long)CCH * NPIX;
    int n0 = blockIdx.x * 32, c0 = blockIdx.y * 32;
    int tx = threadIdx.x, ty = threadIdx.y;
    #pragma unroll
    for (int i = 0; i < 4; i++)
        t[ty + i * 8][tx] = xb[(long)(c0 + ty + i * 8) * NPIX + n0 + tx];
    __syncthreads();
    long sb_ = b * (long)CCH * NPIX;
    #pragma unroll
    for (int i = 0; i < 4; i++) {
        float f = t[ty + i * 8][tx];
        __half h, l; split_h(f, h, l);
        long idx = sb_ + (long)(c0 + ty + i * 8) * NPIX + n0 + tx;
        xh[idx] = h; xl[idx] = l;
        float ft = t[tx][ty + i * 8];
        long idxT = sb_ + (long)(n0 + ty + i * 8) * CCH + c0 + tx;
        xTh[idxT] = __float2half_rn(ft);
    }
}

__global__ void cvt_pair_h(const float4* __restrict__ in, uint2* __restrict__ oh,
                           uint2* __restrict__ ol, int n4)
{
    int i = blockIdx.x * 256 + threadIdx.x;
    if (i >= n4) return;
    float4 v = in[i];
    float f[4] = {v.x, v.y, v.z, v.w};
    uint16_t hh[4], ll[4];
    #pragma unroll
    for (int j = 0; j < 4; j++) {
        __half h, l; split_h(f[j], h, l);
        hh[j] = __half_as_ushort(h);
        ll[j] = __half_as_ushort(l);
    }
    uint2 uh, ul;
    uh.x = hh[0] | ((uint32_t)hh[1] << 16); uh.y = hh[2] | ((uint32_t)hh[3] << 16);
    ul.x = ll[0] | ((uint32_t)ll[1] << 16); ul.y = ll[2] | ((uint32_t)ll[3] << 16);
    oh[i] = uh; ol[i] = ul;
}

// transpose fp32 -> half hi (+ optional lo)
__global__ void transpose_cvt_h(const float* __restrict__ in, __half* __restrict__ oh,
                                __half* __restrict__ ol, int ldin, int ldout,
                                long sIn, long sOut)
{
    __shared__ float t[32][33];
    long b = blockIdx.z;
    in += b * sIn; oh += b * sOut;
    if (ol) ol += b * sOut;
    int x0 = blockIdx.x * 32, y0 = blockIdx.y * 32;
    int tx = threadIdx.x, ty = threadIdx.y;
    #pragma unroll
    for (int i = 0; i < 4; i++)
        t[ty + i * 8][tx] = in[(long)(y0 + ty + i * 8) * ldin + x0 + tx];
    __syncthreads();
    #pragma unroll
    for (int i = 0; i < 4; i++) {
        float v = t[tx][ty + i * 8];
        __half h = __float2half_rn(v);
        long idx = (long)(x0 + ty + i * 8) * ldout + y0 + tx;
        oh[idx] = h;
        if (ol) ol[idx] = __float2half_rn(v - __half2float(h));
    }
}

__global__ void qsum_kernel(const float* __restrict__ q)
{
    int d = blockIdx.x;
    float s = 0.f;
    for (int n = threadIdx.x; n < NPIX; n += 256)
        s += q[(long)d * NPIX + n];
    #pragma unroll
    for (int o = 16; o; o >>= 1) s += __shfl_xor_sync(0xffffffffu, s, o);
    __shared__ float sh[8];
    if ((threadIdx.x & 31) == 0) sh[threadIdx.x >> 5] = s;
    __syncthreads();
    if (threadIdx.x == 0) {
        float t = 0.f;
        #pragma unroll
        for (int i = 0; i < 8; i++) t += sh[i];
        g_qsum[d] = t;
    }
}

__global__ void softmax_kernel()
{
    float* row = g_E + (long)blockIdx.x * CCH;
    int t = threadIdx.x;
    float v0 = row[t], v1 = row[t + 256];
    __shared__ float sh[8];
    float m = fmaxf(v0, v1);
    #pragma unroll
    for (int o = 16; o; o >>= 1) m = fmaxf(m, __shfl_xor_sync(0xffffffffu, m, o));
    if ((t & 31) == 0) sh[t >> 5] = m;
    __syncthreads();
    float mm = sh[0];
    #pragma unroll
    for (int i = 1; i < 8; i++) mm = fmaxf(mm, sh[i]);
    float e0 = expf(v0 - mm), e1 = expf(v1 - mm);
    float s = e0 + e1;
    #pragma unroll
    for (int o = 16; o; o >>= 1) s += __shfl_xor_sync(0xffffffffu, s, o);
    __syncthreads();
    if ((t & 31) == 0) sh[t >> 5] = s;
    __syncthreads();
    float ss = 0.f;
    #pragma unroll
    for (int i = 0; i < 8; i++) ss += sh[i];
    float inv = 1.f / ss;
    row[t]       = e0 * inv;
    row[t + 256] = e1 * inv;
}

__global__ void bias2_kernel(const float* __restrict__ vb)
{
    int idx = blockIdx.x * 256 + threadIdx.x;
    int b = idx >> 9, c = idx & 511;
    const float* att = g_E + (long)b * CCH * CCH;
    float s = 0.f;
    #pragma unroll 4
    for (int d = 0; d < CCH; d++)
        s += att[(long)d * CCH + c] * vb[d];
    g_bias2[idx] = s;
}

// ---------------------------------------------------------------------------
extern "C" void kernel_launch(void* const* d_in, const int* in_sizes, int n_in,
                              void* d_out, int out_size)
{
    const float* x     = (const float*)d_in[0];
    const float* q     = (const float*)d_in[1];
    const float* kw    = (const float*)d_in[2];
    const float* kb    = (const float*)d_in[3];
    const float* vw    = (const float*)d_in[4];
    const float* vb    = (const float*)d_in[5];
    const float* gamma = (const float*)d_in[6];
    float* out = (float*)d_out;

    const int SM3 = 3 * 4 * TILEB;   // 122880
    const int SM1 = 3 * 2 * TILEB;   // 61440
    cudaFuncSetAttribute(gemm_f16<3,0>, cudaFuncAttributeMaxDynamicSharedMemorySize, SM3);
    cudaFuncSetAttribute(gemm_f16<3,1>, cudaFuncAttributeMaxDynamicSharedMemorySize, SM3);
    cudaFuncSetAttribute(gemm_f16<1,3>, cudaFuncAttributeMaxDynamicSharedMemorySize, SM1);
    cudaFuncSetAttribute(gemm_f16<1,2>, cudaFuncAttributeMaxDynamicSharedMemorySize, SM1);

    __half *xh, *xl, *xTh, *qh, *ql, *kwh, *kwl, *vwTh;
    __half *Ph, *Pl, *aTh, *W2h;
    float *pE, *pq, *pb2;
    cudaGetSymbolAddress((void**)&xh,  g_xh);   cudaGetSymbolAddress((void**)&xl,  g_xl);
    cudaGetSymbolAddress((void**)&xTh, g_xTh);
    cudaGetSymbolAddress((void**)&qh,  g_qh);   cudaGetSymbolAddress((void**)&ql,  g_ql);
    cudaGetSymbolAddress((void**)&kwh, g_kwh);  cudaGetSymbolAddress((void**)&kwl, g_kwl);
    cudaGetSymbolAddress((void**)&vwTh,g_vwTh);
    cudaGetSymbolAddress((void**)&Ph,  g_Ph);   cudaGetSymbolAddress((void**)&Pl,  g_Pl);
    cudaGetSymbolAddress((void**)&aTh, g_aTh);  cudaGetSymbolAddress((void**)&W2h, g_W2h);
    cudaGetSymbolAddress((void**)&pE,  g_E);
    cudaGetSymbolAddress((void**)&pq,  g_qsum);
    cudaGetSymbolAddress((void**)&pb2, g_bias2);

    const long sCC = (long)CCH * CCH;
    const long sCN = (long)CCH * NPIX;

    // ---- prep ----
    qsum_kernel<<<CCH, 256>>>(q);
    xprep_kernel<<<dim3(NPIX/32, CCH/32, BATCH), dim3(32,8)>>>(x, xh, xl, xTh);
    cvt_pair_h<<<(CCH*NPIX/4)/256, 256>>>((const float4*)q, (uint2*)qh, (uint2*)ql, CCH*NPIX/4);
    cvt_pair_h<<<(CCH*CCH/4)/256, 256>>>((const float4*)kw, (uint2*)kwh, (uint2*)kwl, CCH*CCH/4);
    transpose_cvt_h<<<dim3(CCH/32, CCH/32, 1), dim3(32,8)>>>(vw, vwTh, (__half*)0, CCH, CCH, 0, 0);

    // ---- GEMM1: P[b][d][c] = sum_n q[d][n]*x[b][c][n]  (3-MMA) ----
    gemm_f16<3,0><<<dim3(4,4,BATCH), 256, SM3>>>(
        qh, ql, xh, xl, NPIX, NPIX, 0, sCN, NPIX,
        Ph, Pl, (float*)0, CCH, sCC,
        (const float*)0, 0, (const float*)0, (const float*)0, (const float*)0);

    // ---- GEMM2: E[b][c][d] = sum_k kw[c][k]*P[b][d][k] + kb[c]*qsum[d] (3-MMA) ----
    gemm_f16<3,1><<<dim3(4,4,BATCH), 256, SM3>>>(
        kwh, kwl, Ph, Pl, CCH, CCH, 0, sCC, CCH,
        (__half*)0, (__half*)0, pE, CCH, sCC,
        kb, 0, pq, (const float*)0, (const float*)0);

    // ---- softmax + bias2 + att transpose (hi only) ----
    softmax_kernel<<<BATCH*CCH, 256>>>();
    bias2_kernel<<<(BATCH*CCH)/256, 256>>>(vb);
    transpose_cvt_h<<<dim3(CCH/32, CCH/32, BATCH), dim3(32,8)>>>(pE, aTh, (__half*)0, CCH, CCH, sCC, sCC);

    // ---- GEMM3: W2[b][c][o] = sum_d attT[c][d]*vwT[o][d]  (1-MMA) ----
    gemm_f16<1,3><<<dim3(4,4,BATCH), 256, SM1>>>(
        aTh, (__half*)0, vwTh, (__half*)0, CCH, CCH, sCC, 0, CCH,
        W2h, (__half*)0, (float*)0, CCH, sCC,
        (const float*)0, 0, (const float*)0, (const float*)0, (const float*)0);

    // ---- GEMM4: out = gamma*(W2 @ xT + bias2) + x  (1-MMA) ----
    gemm_f16<1,2><<<dim3(NPIX/128, 4, BATCH), 256, SM1>>>(
        W2h, (__half*)0, xTh, (__half*)0, CCH, CCH, sCC, sCN, CCH,
        (__half*)0, (__half*)0, out, NPIX, sCN,
        pb2, CCH, (const float*)0, x, gamma);
}

// round 7
// speedup vs baseline: 8.1067x; 1.4437x over previous
#include <cuda_runtime.h>
#include <cuda_fp16.h>
#include <stdint.h>

// ---------------------------------------------------------------------------
// Channel attention, factorized; classic tensor cores mma.m16n8k16 fp16->f32,
// plain fp16 operands everywhere (fp32 accumulate). Peaked softmax (energy
// std ~29 over 512-way) makes pre-softmax energies robust to fp16-level noise.
//   P[b]  = q @ x[b]^T
//   E[b]  = kw . P[b] + kb (x) qsum     (f32 epilogue)
//   att   = softmax rows(E)             (f32)
//   W2[b] = attT . vwT
//   out   = gamma*(W2 @ xT + b2) + x    (f32 epilogue + residual)
// ---------------------------------------------------------------------------

#define BATCH 8
#define CCH   512
#define NPIX  4096

__device__ __half g_xh [BATCH*CCH*NPIX];
__device__ __half g_xTh[BATCH*CCH*NPIX];
__device__ __half g_qh [CCH*NPIX];
__device__ __half g_kwh[CCH*CCH];
__device__ __half g_vwTh[CCH*CCH];
__device__ __half g_Ph [BATCH*CCH*CCH];
__device__ __half g_aTh[BATCH*CCH*CCH];
__device__ __half g_W2h[BATCH*CCH*CCH];
__device__ float g_E[BATCH*CCH*CCH];
__device__ float g_qsum[CCH];
__device__ float g_bias2[BATCH*CCH];

// --------------------------- asm helpers -----------------------------------
__device__ __forceinline__ uint32_t smem_u32(const void* p) {
    uint32_t a;
    asm("{ .reg .u64 t; cvta.to.shared.u64 t, %1; cvt.u32.u64 %0, t; }" : "=r"(a) : "l"(p));
    return a;
}
__device__ __forceinline__ void cp16(uint32_t saddr, const void* g) {
    asm volatile("cp.async.cg.shared.global [%0], [%1], 16;" :: "r"(saddr), "l"(g) : "memory");
}
__device__ __forceinline__ void cp_commit() {
    asm volatile("cp.async.commit_group;" ::: "memory");
}
template<int N>
__device__ __forceinline__ void cp_wait() {
    asm volatile("cp.async.wait_group %0;" :: "n"(N) : "memory");
}
__device__ __forceinline__ void ldsm4(uint32_t* r, uint32_t a) {
    asm volatile("ldmatrix.sync.aligned.m8n8.x4.shared.b16 {%0,%1,%2,%3}, [%4];"
                 : "=r"(r[0]), "=r"(r[1]), "=r"(r[2]), "=r"(r[3]) : "r"(a));
}
__device__ __forceinline__ void mma16816(float* d, const uint32_t* a, const uint32_t* b) {
    asm volatile("mma.sync.aligned.m16n8k16.row.col.f32.f16.f16.f32 "
                 "{%0,%1,%2,%3}, {%4,%5,%6,%7}, {%8,%9}, {%0,%1,%2,%3};"
                 : "+f"(d[0]), "+f"(d[1]), "+f"(d[2]), "+f"(d[3])
                 : "r"(a[0]), "r"(a[1]), "r"(a[2]), "r"(a[3]), "r"(b[0]), "r"(b[1]));
}

// --------------------------- GEMM kernel -----------------------------------
// CTA tile 128x128, BK=32, 3-stage cp.async pipeline, 1 sync per chunk.
// SMEM tile: 128 rows x 32 halves, row padded to 80B. 2 tiles/stage (A,B).
#define RSB   80
#define TILEB 10240
#define STGB  (2*TILEB)
#define GSMEM (3*STGB)    // 61440

// EPI: 1 = f32 + e1[m]*e2[n]; 2 = gamma*(v+e1)+xres; 3 = half out.
template<int EPI>
__global__ __launch_bounds__(256)
void gemm_f16(const __half* __restrict__ Ah, const __half* __restrict__ Bh,
              int ldA, int ldB, long sA, long sB, int K,
              __half* __restrict__ Dh,
              float* __restrict__ Dout, int ldD, long sD,
              const float* __restrict__ e1, long se1,
              const float* __restrict__ e2,
              const float* __restrict__ xres,
              const float* __restrict__ gptr)
{
    extern __shared__ char sm[];
    const uint32_t sb = smem_u32(sm);
    const int tid = threadIdx.x, lane = tid & 31, wid = tid >> 5;
    const int wm = (wid >> 2) * 64, wn = (wid & 3) * 32;
    const int b  = blockIdx.z;
    const int m0 = blockIdx.y * 128, n0 = blockIdx.x * 128;

    Ah += b * sA;
    Bh += b * sB;

    const uint32_t aoff = ((lane & 7) + 8 * ((lane >> 3) & 1)) * RSB + (lane >> 4) * 16;
    const uint32_t boff = ((lane & 7) + 8 * (lane >> 4)) * RSB + ((lane >> 3) & 1) * 16;

    const int r0c = tid >> 2;
    const int c16 = tid & 3;

    float acc[4][4][4];
    #pragma unroll
    for (int i = 0; i < 4; i++)
        #pragma unroll
        for (int j = 0; j < 4; j++)
            #pragma unroll
            for (int v = 0; v < 4; v++) acc[i][j][v] = 0.f;

    const int nc = K >> 5;

    auto load_stage = [&](int stage, int k0) {
        uint32_t base = sb + stage * STGB;
        #pragma unroll
        for (int i = 0; i < 2; i++) {
            int row = r0c + i * 64;
            uint32_t so = base + row * RSB + c16 * 16;
            cp16(so,         Ah + (long)(m0 + row) * ldA + k0 + c16 * 8);
            cp16(so + TILEB, Bh + (long)(n0 + row) * ldB + k0 + c16 * 8);
        }
    };

    auto compute_stage = [&](int stage) {
        uint32_t Abase = sb + stage * STGB;
        uint32_t Bbase = Abase + TILEB;
        #pragma unroll
        for (int ks = 0; ks < 2; ks++) {
            uint32_t kb2 = ks * 32;
            uint32_t ah[4][4], bh[4][2];
            #pragma unroll
            for (int mi = 0; mi < 4; mi++)
                ldsm4(ah[mi], Abase + (wm + mi * 16) * RSB + kb2 + aoff);
            #pragma unroll
            for (int nb = 0; nb < 2; nb++) {
                uint32_t t[4];
                ldsm4(t, Bbase + (wn + nb * 16) * RSB + kb2 + boff);
                bh[2*nb][0] = t[0]; bh[2*nb][1] = t[1];
                bh[2*nb+1][0] = t[2]; bh[2*nb+1][1] = t[3];
            }
            #pragma unroll
            for (int mi = 0; mi < 4; mi++)
                #pragma unroll
                for (int ni = 0; ni < 4; ni++)
                    mma16816(acc[mi][ni], ah[mi], bh[ni]);
        }
    };

    // 3-stage pipeline
    load_stage(0, 0);
    cp_commit();
    if (nc > 1) load_stage(1, 32);
    cp_commit();
    for (int c = 0; c < nc; c++) {
        cp_wait<1>();
        __syncthreads();
        if (c + 2 < nc) load_stage((c + 2) % 3, (c + 2) * 32);
        cp_commit();
        compute_stage(c % 3);
    }

    // ------------------------------ epilogue -------------------------------
    float g = 0.f;
    if (EPI == 2) g = gptr[0];
    #pragma unroll
    for (int mi = 0; mi < 4; mi++) {
        #pragma unroll
        for (int half_ = 0; half_ < 2; half_++) {
            int r = m0 + wm + mi * 16 + (lane >> 2) + half_ * 8;
            float e1r = 0.f;
            if (EPI == 1) e1r = e1[r];
            if (EPI == 2) e1r = e1[b * se1 + r];
            #pragma unroll
            for (int ni = 0; ni < 4; ni++) {
                int cidx = n0 + wn + ni * 8 + 2 * (lane & 3);
                float v0 = acc[mi][ni][half_ * 2 + 0];
                float v1 = acc[mi][ni][half_ * 2 + 1];
                long idx = (long)r * ldD + cidx;
                if (EPI == 3) {
                    __half2 ph;
                    ph.x = __float2half_rn(v0); ph.y = __float2half_rn(v1);
                    *reinterpret_cast<__half2*>(Dh + b * sD + idx) = ph;
                } else if (EPI == 1) {
                    float2 o;
                    o.x = v0 + e1r * e2[cidx];
                    o.y = v1 + e1r * e2[cidx + 1];
                    *reinterpret_cast<float2*>(Dout + b * sD + idx) = o;
                } else {
                    float2 xr = *reinterpret_cast<const float2*>(xres + b * sD + idx);
                    float2 o;
                    o.x = g * (v0 + e1r) + xr.x;
                    o.y = g * (v1 + e1r) + xr.y;
                    *reinterpret_cast<float2*>(Dout + b * sD + idx) = o;
                }
            }
        }
    }
}

// ------------------------- prep kernels ------------------------------------
// fused convert + transpose for x: writes xh (CxN) and xTh (NxC), both fp16
__global__ void xprep_kernel(const float* __restrict__ x,
                             __half* __restrict__ xh, __half* __restrict__ xTh)
{
    __shared__ float t[32][33];
    long b = blockIdx.z;
    const float* xb = x + b * (long)CCH * NPIX;
    int n0 = blockIdx.x * 32, c0 = blockIdx.y * 32;
    int tx = threadIdx.x, ty = threadIdx.y;
    #pragma unroll
    for (int i = 0; i < 4; i++)
        t[ty + i * 8][tx] = xb[(long)(c0 + ty + i * 8) * NPIX + n0 + tx];
    __syncthreads();
    long sb_ = b * (long)CCH * NPIX;
    #pragma unroll
    for (int i = 0; i < 4; i++) {
        float f = t[ty + i * 8][tx];
        long idx = sb_ + (long)(c0 + ty + i * 8) * NPIX + n0 + tx;
        xh[idx] = __float2half_rn(f);
        float ft = t[tx][ty + i * 8];
        long idxT = sb_ + (long)(n0 + ty + i * 8) * CCH + c0 + tx;
        xTh[idxT] = __float2half_rn(ft);
    }
}

__global__ void cvt_h(const float4* __restrict__ in, uint2* __restrict__ oh, int n4)
{
    int i = blockIdx.x * 256 + threadIdx.x;
    if (i >= n4) return;
    float4 v = in[i];
    uint16_t hh[4];
    hh[0] = __half_as_ushort(__float2half_rn(v.x));
    hh[1] = __half_as_ushort(__float2half_rn(v.y));
    hh[2] = __half_as_ushort(__float2half_rn(v.z));
    hh[3] = __half_as_ushort(__float2half_rn(v.w));
    uint2 uh;
    uh.x = hh[0] | ((uint32_t)hh[1] << 16);
    uh.y = hh[2] | ((uint32_t)hh[3] << 16);
    oh[i] = uh;
}

// transpose fp32 -> fp16
__global__ void transpose_cvt_h(const float* __restrict__ in, __half* __restrict__ oh,
                                int ldin, int ldout, long sIn, long sOut)
{
    __shared__ float t[32][33];
    long b = blockIdx.z;
    in += b * sIn; oh += b * sOut;
    int x0 = blockIdx.x * 32, y0 = blockIdx.y * 32;
    int tx = threadIdx.x, ty = threadIdx.y;
    #pragma unroll
    for (int i = 0; i < 4; i++)
        t[ty + i * 8][tx] = in[(long)(y0 + ty + i * 8) * ldin + x0 + tx];
    __syncthreads();
    #pragma unroll
    for (int i = 0; i < 4; i++) {
        float v = t[tx][ty + i * 8];
        oh[(long)(x0 + ty + i * 8) * ldout + y0 + tx] = __float2half_rn(v);
    }
}

__global__ void qsum_kernel(const float* __restrict__ q)
{
    int d = blockIdx.x;
    float s = 0.f;
    for (int n = threadIdx.x; n < NPIX; n += 256)
        s += q[(long)d * NPIX + n];
    #pragma unroll
    for (int o = 16; o; o >>= 1) s += __shfl_xor_sync(0xffffffffu, s, o);
    __shared__ float sh[8];
    if ((threadIdx.x & 31) == 0) sh[threadIdx.x >> 5] = s;
    __syncthreads();
    if (threadIdx.x == 0) {
        float t = 0.f;
        #pragma unroll
        for (int i = 0; i < 8; i++) t += sh[i];
        g_qsum[d] = t;
    }
}

__global__ void softmax_kernel()
{
    float* row = g_E + (long)blockIdx.x * CCH;
    int t = threadIdx.x;
    float v0 = row[t], v1 = row[t + 256];
    __shared__ float sh[8];
    float m = fmaxf(v0, v1);
    #pragma unroll
    for (int o = 16; o; o >>= 1) m = fmaxf(m, __shfl_xor_sync(0xffffffffu, m, o));
    if ((t & 31) == 0) sh[t >> 5] = m;
    __syncthreads();
    float mm = sh[0];
    #pragma unroll
    for (int i = 1; i < 8; i++) mm = fmaxf(mm, sh[i]);
    float e0 = expf(v0 - mm), e1 = expf(v1 - mm);
    float s = e0 + e1;
    #pragma unroll
    for (int o = 16; o; o >>= 1) s += __shfl_xor_sync(0xffffffffu, s, o);
    __syncthreads();
    if ((t & 31) == 0) sh[t >> 5] = s;
    __syncthreads();
    float ss = 0.f;
    #pragma unroll
    for (int i = 0; i < 8; i++) ss += sh[i];
    float inv = 1.f / ss;
    row[t]       = e0 * inv;
    row[t + 256] = e1 * inv;
}

__global__ void bias2_kernel(const float* __restrict__ vb)
{
    int idx = blockIdx.x * 256 + threadIdx.x;
    int b = idx >> 9, c = idx & 511;
    const float* att = g_E + (long)b * CCH * CCH;
    float s = 0.f;
    #pragma unroll 4
    for (int d = 0; d < CCH; d++)
        s += att[(long)d * CCH + c] * vb[d];
    g_bias2[idx] = s;
}

// ---------------------------------------------------------------------------
extern "C" void kernel_launch(void* const* d_in, const int* in_sizes, int n_in,
                              void* d_out, int out_size)
{
    const float* x     = (const float*)d_in[0];
    const float* q     = (const float*)d_in[1];
    const float* kw    = (const float*)d_in[2];
    const float* kb    = (const float*)d_in[3];
    const float* vw    = (const float*)d_in[4];
    const float* vb    = (const float*)d_in[5];
    const float* gamma = (const float*)d_in[6];
    float* out = (float*)d_out;

    cudaFuncSetAttribute(gemm_f16<1>, cudaFuncAttributeMaxDynamicSharedMemorySize, GSMEM);
    cudaFuncSetAttribute(gemm_f16<2>, cudaFuncAttributeMaxDynamicSharedMemorySize, GSMEM);
    cudaFuncSetAttribute(gemm_f16<3>, cudaFuncAttributeMaxDynamicSharedMemorySize, GSMEM);

    __half *xh, *xTh, *qh, *kwh, *vwTh, *Ph, *aTh, *W2h;
    float *pE, *pq, *pb2;
    cudaGetSymbolAddress((void**)&xh,  g_xh);
    cudaGetSymbolAddress((void**)&xTh, g_xTh);
    cudaGetSymbolAddress((void**)&qh,  g_qh);
    cudaGetSymbolAddress((void**)&kwh, g_kwh);
    cudaGetSymbolAddress((void**)&vwTh,g_vwTh);
    cudaGetSymbolAddress((void**)&Ph,  g_Ph);
    cudaGetSymbolAddress((void**)&aTh, g_aTh);
    cudaGetSymbolAddress((void**)&W2h, g_W2h);
    cudaGetSymbolAddress((void**)&pE,  g_E);
    cudaGetSymbolAddress((void**)&pq,  g_qsum);
    cudaGetSymbolAddress((void**)&pb2, g_bias2);

    const long sCC = (long)CCH * CCH;
    const long sCN = (long)CCH * NPIX;

    // ---- prep ----
    qsum_kernel<<<CCH, 256>>>(q);
    xprep_kernel<<<dim3(NPIX/32, CCH/32, BATCH), dim3(32,8)>>>(x, xh, xTh);
    cvt_h<<<(CCH*NPIX/4)/256, 256>>>((const float4*)q, (uint2*)qh, CCH*NPIX/4);
    cvt_h<<<(CCH*CCH/4)/256, 256>>>((const float4*)kw, (uint2*)kwh, CCH*CCH/4);
    transpose_cvt_h<<<dim3(CCH/32, CCH/32, 1), dim3(32,8)>>>(vw, vwTh, CCH, CCH, 0, 0);

    // ---- GEMM1: P[b][d][c] = sum_n q[d][n]*x[b][c][n] ----
    gemm_f16<3><<<dim3(4,4,BATCH), 256, GSMEM>>>(
        qh, xh, NPIX, NPIX, 0, sCN, NPIX,
        Ph, (float*)0, CCH, sCC,
        (const float*)0, 0, (const float*)0, (const float*)0, (const float*)0);

    // ---- GEMM2: E[b][c][d] = sum_k kw[c][k]*P[b][d][k] + kb[c]*qsum[d] ----
    gemm_f16<1><<<dim3(4,4,BATCH), 256, GSMEM>>>(
        kwh, Ph, CCH, CCH, 0, sCC, CCH,
        (__half*)0, pE, CCH, sCC,
        kb, 0, pq, (const float*)0, (const float*)0);

    // ---- softmax + bias2 + att transpose ----
    softmax_kernel<<<BATCH*CCH, 256>>>();
    bias2_kernel<<<(BATCH*CCH)/256, 256>>>(vb);
    transpose_cvt_h<<<dim3(CCH/32, CCH/32, BATCH), dim3(32,8)>>>(pE, aTh, CCH, CCH, sCC, sCC);

    // ---- GEMM3: W2[b][c][o] = sum_d attT[c][d]*vwT[o][d] ----
    gemm_f16<3><<<dim3(4,4,BATCH), 256, GSMEM>>>(
        aTh, vwTh, CCH, CCH, sCC, 0, CCH,
        W2h, (float*)0, CCH, sCC,
        (const float*)0, 0, (const float*)0, (const float*)0, (const float*)0);

    // ---- GEMM4: out = gamma*(W2 @ xT + bias2) + x ----
    gemm_f16<2><<<dim3(NPIX/128, 4, BATCH), 256, GSMEM>>>(
        W2h, xTh, CCH, CCH, sCC, sCN, CCH,
        (__half*)0, out, NPIX, sCN,
        pb2, CCH, (const float*)0, x, gamma);
}

// round 8
// speedup vs baseline: 10.2286x; 1.2618x over previous
#include <cuda_runtime.h>
#include <cuda_fp16.h>
#include <stdint.h>

// ---------------------------------------------------------------------------
// Channel attention, factorized; classic tensor cores mma.m16n8k16 fp16->f32.
//   P[b]  = q @ x[b]^T                   1-MMA fp16
//   E[b]  = kw . P[b] + kb (x) qsum      2-MMA (kw hi/lo split)
//   att   = softmax rows(E)              fused with transpose -> aTh fp16
//   W2[b] = attT . vwT                   1-MMA
//   out   = gamma*(W2 @ xT + b2) + x     1-MMA, f32 epilogue + residual
// ---------------------------------------------------------------------------

#define BATCH 8
#define CCH   512
#define NPIX  4096

__device__ __half g_xh [BATCH*CCH*NPIX];
__device__ __half g_xTh[BATCH*CCH*NPIX];
__device__ __half g_qh [CCH*NPIX];
__device__ __half g_kwh[CCH*CCH];
__device__ __half g_kwl[CCH*CCH];
__device__ __half g_vwTh[CCH*CCH];
__device__ __half g_Ph [BATCH*CCH*CCH];
__device__ __half g_aTh[BATCH*CCH*CCH];
__device__ __half g_W2h[BATCH*CCH*CCH];
__device__ float g_E[BATCH*CCH*CCH];
__device__ float g_qsum[CCH];
__device__ float g_bias2[BATCH*CCH];

// --------------------------- asm helpers -----------------------------------
__device__ __forceinline__ uint32_t smem_u32(const void* p) {
    uint32_t a;
    asm("{ .reg .u64 t; cvta.to.shared.u64 t, %1; cvt.u32.u64 %0, t; }" : "=r"(a) : "l"(p));
    return a;
}
__device__ __forceinline__ void cp16(uint32_t saddr, const void* g) {
    asm volatile("cp.async.cg.shared.global [%0], [%1], 16;" :: "r"(saddr), "l"(g) : "memory");
}
__device__ __forceinline__ void cp_commit() {
    asm volatile("cp.async.commit_group;" ::: "memory");
}
template<int N>
__device__ __forceinline__ void cp_wait() {
    asm volatile("cp.async.wait_group %0;" :: "n"(N) : "memory");
}
__device__ __forceinline__ void ldsm4(uint32_t* r, uint32_t a) {
    asm volatile("ldmatrix.sync.aligned.m8n8.x4.shared.b16 {%0,%1,%2,%3}, [%4];"
                 : "=r"(r[0]), "=r"(r[1]), "=r"(r[2]), "=r"(r[3]) : "r"(a));
}
__device__ __forceinline__ void mma16816(float* d, const uint32_t* a, const uint32_t* b) {
    asm volatile("mma.sync.aligned.m16n8k16.row.col.f32.f16.f16.f32 "
                 "{%0,%1,%2,%3}, {%4,%5,%6,%7}, {%8,%9}, {%0,%1,%2,%3};"
                 : "+f"(d[0]), "+f"(d[1]), "+f"(d[2]), "+f"(d[3])
                 : "r"(a[0]), "r"(a[1]), "r"(a[2]), "r"(a[3]), "r"(b[0]), "r"(b[1]));
}
__device__ __forceinline__ uint32_t pack2(__half a, __half b) {
    __half2 p; p.x = a; p.y = b;
    return *reinterpret_cast<uint32_t*>(&p);
}

// --------------------------- GEMM kernel -----------------------------------
// CTA tile 128x128, BK=32, 3-stage cp.async pipeline.
// SMEM tile: 128 rows x 32 halves, row padded to 80B.
// NMMA=1: tiles A,B.  NMMA=2: A-split (Ah, Al) + B.
#define RSB   80
#define TILEB 10240

// EPI: 1 = f32 + e1[m]*e2[n]; 2 = gamma*(v+e1)+xres; 3 = half out.
template<int NMMA, int EPI>
__global__ __launch_bounds__(256)
void gemm_f16(const __half* __restrict__ Ah, const __half* __restrict__ Al,
              const __half* __restrict__ Bh,
              int ldA, int ldB, long sA, long sB, int K,
              __half* __restrict__ Dh,
              float* __restrict__ Dout, int ldD, long sD,
              const float* __restrict__ e1, long se1,
              const float* __restrict__ e2,
              const float* __restrict__ xres,
              const float* __restrict__ gptr)
{
    constexpr int NTILES = (NMMA == 2) ? 3 : 2;
    constexpr int STGB   = NTILES * TILEB;
    constexpr int BOFF   = (NMMA == 2) ? 2 * TILEB : TILEB;

    extern __shared__ char sm[];
    const uint32_t sb = smem_u32(sm);
    const int tid = threadIdx.x, lane = tid & 31, wid = tid >> 5;
    const int wm = (wid >> 2) * 64, wn = (wid & 3) * 32;
    const int b  = blockIdx.z;
    const int m0 = blockIdx.y * 128, n0 = blockIdx.x * 128;

    Ah += b * sA;
    Bh += b * sB;

    const uint32_t aoff = ((lane & 7) + 8 * ((lane >> 3) & 1)) * RSB + (lane >> 4) * 16;
    const uint32_t boff = ((lane & 7) + 8 * (lane >> 4)) * RSB + ((lane >> 3) & 1) * 16;

    const int r0c = tid >> 2;
    const int c16 = tid & 3;

    float acc[4][4][4];
    #pragma unroll
    for (int i = 0; i < 4; i++)
        #pragma unroll
        for (int j = 0; j < 4; j++)
            #pragma unroll
            for (int v = 0; v < 4; v++) acc[i][j][v] = 0.f;

    const int nc = K >> 5;

    auto load_stage = [&](int stage, int k0) {
        uint32_t base = sb + stage * STGB;
        #pragma unroll
        for (int i = 0; i < 2; i++) {
            int row = r0c + i * 64;
            uint32_t so = base + row * RSB + c16 * 16;
            long ga = (long)(m0 + row) * ldA + k0 + c16 * 8;
            cp16(so, Ah + ga);
            if (NMMA == 2) cp16(so + TILEB, Al + ga);
            cp16(so + BOFF, Bh + (long)(n0 + row) * ldB + k0 + c16 * 8);
        }
    };

    auto compute_stage = [&](int stage) {
        uint32_t Abase = sb + stage * STGB;
        uint32_t Bbase = Abase + BOFF;
        #pragma unroll
        for (int ks = 0; ks < 2; ks++) {
            uint32_t kb2 = ks * 32;
            uint32_t ah[4][4], al[4][4], bh[4][2];
            #pragma unroll
            for (int mi = 0; mi < 4; mi++) {
                ldsm4(ah[mi], Abase + (wm + mi * 16) * RSB + kb2 + aoff);
                if (NMMA == 2) ldsm4(al[mi], Abase + TILEB + (wm + mi * 16) * RSB + kb2 + aoff);
            }
            #pragma unroll
            for (int nb = 0; nb < 2; nb++) {
                uint32_t t[4];
                ldsm4(t, Bbase + (wn + nb * 16) * RSB + kb2 + boff);
                bh[2*nb][0] = t[0]; bh[2*nb][1] = t[1];
                bh[2*nb+1][0] = t[2]; bh[2*nb+1][1] = t[3];
            }
            #pragma unroll
            for (int mi = 0; mi < 4; mi++)
                #pragma unroll
                for (int ni = 0; ni < 4; ni++) {
                    mma16816(acc[mi][ni], ah[mi], bh[ni]);
                    if (NMMA == 2) mma16816(acc[mi][ni], al[mi], bh[ni]);
                }
        }
    };

    load_stage(0, 0);
    cp_commit();
    if (nc > 1) load_stage(1, 32);
    cp_commit();
    for (int c = 0; c < nc; c++) {
        cp_wait<1>();
        __syncthreads();
        if (c + 2 < nc) load_stage((c + 2) % 3, (c + 2) * 32);
        cp_commit();
        compute_stage(c % 3);
    }

    // ------------------------------ epilogue -------------------------------
    float g = 0.f;
    if (EPI == 2) g = gptr[0];
    #pragma unroll
    for (int mi = 0; mi < 4; mi++) {
        #pragma unroll
        for (int half_ = 0; half_ < 2; half_++) {
            int r = m0 + wm + mi * 16 + (lane >> 2) + half_ * 8;
            float e1r = 0.f;
            if (EPI == 1) e1r = e1[r];
            if (EPI == 2) e1r = e1[b * se1 + r];
            #pragma unroll
            for (int ni = 0; ni < 4; ni++) {
                int cidx = n0 + wn + ni * 8 + 2 * (lane & 3);
                float v0 = acc[mi][ni][half_ * 2 + 0];
                float v1 = acc[mi][ni][half_ * 2 + 1];
                long idx = (long)r * ldD + cidx;
                if (EPI == 3) {
                    __half2 ph;
                    ph.x = __float2half_rn(v0); ph.y = __float2half_rn(v1);
                    *reinterpret_cast<__half2*>(Dh + b * sD + idx) = ph;
                } else if (EPI == 1) {
                    float2 o;
                    o.x = v0 + e1r * e2[cidx];
                    o.y = v1 + e1r * e2[cidx + 1];
                    *reinterpret_cast<float2*>(Dout + b * sD + idx) = o;
                } else {
                    float2 xr = *reinterpret_cast<const float2*>(xres + b * sD + idx);
                    float2 o;
                    o.x = g * (v0 + e1r) + xr.x;
                    o.y = g * (v1 + e1r) + xr.y;
                    *reinterpret_cast<float2*>(Dout + b * sD + idx) = o;
                }
            }
        }
    }
}

// ------------------------- prep kernels ------------------------------------
// x: convert to fp16 (CxN) and transposed fp16 (NxC). 64x64 tiles, vector I/O.
__global__ __launch_bounds__(256)
void xprep_kernel(const float* __restrict__ x,
                  __half* __restrict__ xh, __half* __restrict__ xTh)
{
    __shared__ __half t[64][66];
    const int b  = blockIdx.z;
    const int n0 = blockIdx.x * 64, c0 = blockIdx.y * 64;
    const int tx = threadIdx.x & 15, ty = threadIdx.x >> 4;
    const long sb_ = (long)b * CCH * NPIX;
    const float* xb = x + sb_;

    #pragma unroll
    for (int i = 0; i < 4; i++) {
        int cl = ty + 16 * i;
        float4 v = *reinterpret_cast<const float4*>(xb + (long)(c0 + cl) * NPIX + n0 + tx * 4);
        uint32_t p0 = pack2(__float2half_rn(v.x), __float2half_rn(v.y));
        uint32_t p1 = pack2(__float2half_rn(v.z), __float2half_rn(v.w));
        uint2 u; u.x = p0; u.y = p1;
        *reinterpret_cast<uint2*>(xh + sb_ + (long)(c0 + cl) * NPIX + n0 + tx * 4) = u;
        *reinterpret_cast<uint32_t*>(&t[cl][tx * 4])     = p0;
        *reinterpret_cast<uint32_t*>(&t[cl][tx * 4 + 2]) = p1;
    }
    __syncthreads();
    #pragma unroll
    for (int i = 0; i < 4; i++) {
        int nl = ty + 16 * i;
        uint2 u;
        u.x = pack2(t[tx*4+0][nl], t[tx*4+1][nl]);
        u.y = pack2(t[tx*4+2][nl], t[tx*4+3][nl]);
        *reinterpret_cast<uint2*>(xTh + sb_ + (long)(n0 + nl) * CCH + c0 + tx * 4) = u;
    }
}

// q: convert to fp16 + row sums (qsum). One block per d row.
__global__ __launch_bounds__(256)
void qprep_kernel(const float* __restrict__ q, __half* __restrict__ qh)
{
    const int d = blockIdx.x, tid = threadIdx.x;
    const float4* row = reinterpret_cast<const float4*>(q + (long)d * NPIX);
    uint2* orow = reinterpret_cast<uint2*>(qh + (long)d * NPIX);
    float s = 0.f;
    #pragma unroll
    for (int j = 0; j < 4; j++) {
        int i = tid + j * 256;
        float4 v = row[i];
        s += v.x + v.y + v.z + v.w;
        uint2 u;
        u.x = pack2(__float2half_rn(v.x), __float2half_rn(v.y));
        u.y = pack2(__float2half_rn(v.z), __float2half_rn(v.w));
        orow[i] = u;
    }
    #pragma unroll
    for (int o = 16; o; o >>= 1) s += __shfl_xor_sync(0xffffffffu, s, o);
    __shared__ float sh[8];
    if ((tid & 31) == 0) sh[tid >> 5] = s;
    __syncthreads();
    if (tid == 0) {
        float t = 0.f;
        #pragma unroll
        for (int i = 0; i < 8; i++) t += sh[i];
        g_qsum[d] = t;
    }
}

// kw hi/lo convert (blocks 0..255) + vw transpose->fp16 (blocks 256..511)
__global__ __launch_bounds__(256)
void wprep_kernel(const float* __restrict__ kw, const float* __restrict__ vw,
                  uint2* __restrict__ kwh, uint2* __restrict__ kwl,
                  __half* __restrict__ vwTh)
{
    __shared__ float smf[32][33];
    if (blockIdx.x < 256) {
        int i = blockIdx.x * 256 + threadIdx.x;
        float4 v = reinterpret_cast<const float4*>(kw)[i];
        float f[4] = {v.x, v.y, v.z, v.w};
        __half h[4], l[4];
        #pragma unroll
        for (int j = 0; j < 4; j++) {
            h[j] = __float2half_rn(f[j]);
            l[j] = __float2half_rn(f[j] - __half2float(h[j]));
        }
        uint2 uh, ul;
        uh.x = pack2(h[0], h[1]); uh.y = pack2(h[2], h[3]);
        ul.x = pack2(l[0], l[1]); ul.y = pack2(l[2], l[3]);
        kwh[i] = uh; kwl[i] = ul;
    } else {
        int t = blockIdx.x - 256;
        int x0 = (t & 15) * 32, y0 = (t >> 4) * 32;
        int tx = threadIdx.x & 31, ty = threadIdx.x >> 5;
        #pragma unroll
        for (int i = 0; i < 4; i++)
            smf[ty + i * 8][tx] = vw[(long)(y0 + ty + i * 8) * CCH + x0 + tx];
        __syncthreads();
        #pragma unroll
        for (int i = 0; i < 4; i++)
            vwTh[(long)(x0 + ty + i * 8) * CCH + y0 + tx] = __float2half_rn(smf[tx][ty + i * 8]);
    }
}

// fused softmax (rows of g_E) + transposed fp16 write to aTh
__global__ __launch_bounds__(256)
void smtrans_kernel(__half* __restrict__ aTh)
{
    __shared__ __half s[8][512];
    const int w = threadIdx.x >> 5, lane = threadIdx.x & 31;
    const long r = (long)blockIdx.x * 8 + w;
    const float* row = g_E + r * CCH;

    float v[16];
    float m = -1e30f;
    #pragma unroll
    for (int k = 0; k < 16; k++) { v[k] = row[lane + 32 * k]; m = fmaxf(m, v[k]); }
    #pragma unroll
    for (int o = 16; o; o >>= 1) m = fmaxf(m, __shfl_xor_sync(0xffffffffu, m, o));
    float ss = 0.f;
    #pragma unroll
    for (int k = 0; k < 16; k++) { v[k] = expf(v[k] - m); ss += v[k]; }
    #pragma unroll
    for (int o = 16; o; o >>= 1) ss += __shfl_xor_sync(0xffffffffu, ss, o);
    float inv = 1.f / ss;
    #pragma unroll
    for (int k = 0; k < 16; k++)
        s[w][lane + 32 * k] = __float2half_rn(v[k] * inv);
    __syncthreads();

    const int b  = (blockIdx.x * 8) >> 9;
    const int c0 = (blockIdx.x * 8) & 511;
    __half* out = aTh + (long)b * CCH * CCH + c0;
    #pragma unroll
    for (int dd = 0; dd < 2; dd++) {
        int d = 2 * threadIdx.x + dd;
        uint4 u;
        u.x = pack2(s[0][d], s[1][d]);
        u.y = pack2(s[2][d], s[3][d]);
        u.z = pack2(s[4][d], s[5][d]);
        u.w = pack2(s[6][d], s[7][d]);
        *reinterpret_cast<uint4*>(out + (long)d * CCH) = u;
    }
}

// bias2[b,c] = sum_d aTh[b][c*512+d]*vb[d]   (aTh[c][d] = att[d][c])
__global__ __launch_bounds__(256)
void bias2_kernel(const __half* __restrict__ aTh, const float* __restrict__ vb)
{
    const int row = blockIdx.x * 8 + (threadIdx.x >> 5);   // (b,c)
    const int lane = threadIdx.x & 31;
    const __half* ar = aTh + (long)row * CCH;
    float s = 0.f;
    #pragma unroll
    for (int k = 0; k < 16; k++) {
        int d = lane + 32 * k;
        s += __half2float(ar[d]) * vb[d];
    }
    #pragma unroll
    for (int o = 16; o; o >>= 1) s += __shfl_xor_sync(0xffffffffu, s, o);
    if (lane == 0) g_bias2[row] = s;
}

// ---------------------------------------------------------------------------
extern "C" void kernel_launch(void* const* d_in, const int* in_sizes, int n_in,
                              void* d_out, int out_size)
{
    const float* x     = (const float*)d_in[0];
    const float* q     = (const float*)d_in[1];
    const float* kw    = (const float*)d_in[2];
    const float* kb    = (const float*)d_in[3];
    const float* vw    = (const float*)d_in[4];
    const float* vb    = (const float*)d_in[5];
    const float* gamma = (const float*)d_in[6];
    float* out = (float*)d_out;

    const int SM1 = 3 * 2 * TILEB;   // 61440
    const int SM2 = 3 * 3 * TILEB;   // 92160
    cudaFuncSetAttribute(gemm_f16<1,1>, cudaFuncAttributeMaxDynamicSharedMemorySize, SM1);
    cudaFuncSetAttribute(gemm_f16<1,2>, cudaFuncAttributeMaxDynamicSharedMemorySize, SM1);
    cudaFuncSetAttribute(gemm_f16<1,3>, cudaFuncAttributeMaxDynamicSharedMemorySize, SM1);
    cudaFuncSetAttribute(gemm_f16<2,1>, cudaFuncAttributeMaxDynamicSharedMemorySize, SM2);

    __half *xh, *xTh, *qh, *kwh, *kwl, *vwTh, *Ph, *aTh, *W2h;
    float *pE, *pq, *pb2;
    cudaGetSymbolAddress((void**)&xh,  g_xh);
    cudaGetSymbolAddress((void**)&xTh, g_xTh);
    cudaGetSymbolAddress((void**)&qh,  g_qh);
    cudaGetSymbolAddress((void**)&kwh, g_kwh);
    cudaGetSymbolAddress((void**)&kwl, g_kwl);
    cudaGetSymbolAddress((void**)&vwTh,g_vwTh);
    cudaGetSymbolAddress((void**)&Ph,  g_Ph);
    cudaGetSymbolAddress((void**)&aTh, g_aTh);
    cudaGetSymbolAddress((void**)&W2h, g_W2h);
    cudaGetSymbolAddress((void**)&pE,  g_E);
    cudaGetSymbolAddress((void**)&pq,  g_qsum);
    cudaGetSymbolAddress((void**)&pb2, g_bias2);

    const long sCC = (long)CCH * CCH;
    const long sCN = (long)CCH * NPIX;

    // ---- prep ----
    qprep_kernel<<<CCH, 256>>>(q, qh);
    xprep_kernel<<<dim3(NPIX/64, CCH/64, BATCH), 256>>>(x, xh, xTh);
    wprep_kernel<<<512, 256>>>(kw, vw, (uint2*)kwh, (uint2*)kwl, vwTh);

    // ---- GEMM1: P[b][d][c] = sum_n q[d][n]*x[b][c][n] ----
    gemm_f16<1,3><<<dim3(4,4,BATCH), 256, SM1>>>(
        qh, (const __half*)0, xh, NPIX, NPIX, 0, sCN, NPIX,
        Ph, (float*)0, CCH, sCC,
        (const float*)0, 0, (const float*)0, (const float*)0, (const float*)0);

    // ---- GEMM2: E[b][c][d] = sum_k kw[c][k]*P[b][d][k] + kb[c]*qsum[d] (kw split) ----
    gemm_f16<2,1><<<dim3(4,4,BATCH), 256, SM2>>>(
        kwh, kwl, Ph, CCH, CCH, 0, sCC, CCH,
        (__half*)0, pE, CCH, sCC,
        kb, 0, pq, (const float*)0, (const float*)0);

    // ---- fused softmax + transpose, then bias2 ----
    smtrans_kernel<<<BATCH*CCH/8, 256>>>(aTh);
    bias2_kernel<<<BATCH*CCH/8, 256>>>(aTh, vb);

    // ---- GEMM3: W2[b][c][o] = sum_d attT[c][d]*vwT[o][d] ----
    gemm_f16<1,3><<<dim3(4,4,BATCH), 256, SM1>>>(
        aTh, (const __half*)0, vwTh, CCH, CCH, sCC, 0, CCH,
        W2h, (float*)0, CCH, sCC,
        (const float*)0, 0, (const float*)0, (const float*)0, (const float*)0);

    // ---- GEMM4: out = gamma*(W2 @ xT + bias2) + x ----
    gemm_f16<1,2><<<dim3(NPIX/128, 4, BATCH), 256, SM1>>>(
        W2h, (const __half*)0, xTh, CCH, CCH, sCC, sCN, CCH,
        (__half*)0, out, NPIX, sCN,
        pb2, CCH, (const float*)0, x, gamma);
}

// round 10
// speedup vs baseline: 10.4423x; 1.0209x over previous
#include <cuda_runtime.h>
#include <cuda_fp16.h>
#include <stdint.h>

// ---------------------------------------------------------------------------
// Channel attention, factorized; classic tensor cores mma.m16n8k16 fp16->f32.
//   P[b]  = q @ x[b]^T                   1-MMA fp16, split-K=2 (f32 partials)
//   E[b]  = kw . P[b] + kb (x) qsum      2-MMA (kw hi/lo split)
//   att   = softmax rows(E)              fused with transpose -> aTh fp16
//   W2[b] = attT . vwT                   1-MMA
//   out   = gamma*(W2 @ xT + b2) + x     1-MMA, f32 epilogue + residual
// ---------------------------------------------------------------------------

#define BATCH 8
#define CCH   512
#define NPIX  4096

__device__ __half g_xh [BATCH*CCH*NPIX];
__device__ __half g_xTh[BATCH*CCH*NPIX];
__device__ __half g_qh [CCH*NPIX];
__device__ __half g_kwh[CCH*CCH];
__device__ __half g_kwl[CCH*CCH];
__device__ __half g_vwTh[CCH*CCH];
__device__ __half g_Ph [BATCH*CCH*CCH];
__device__ __half g_aTh[BATCH*CCH*CCH];
__device__ __half g_W2h[BATCH*CCH*CCH];
__device__ float g_Pp[2*BATCH*CCH*CCH];   // split-K partials for GEMM1
__device__ float g_E[BATCH*CCH*CCH];
__device__ float g_qsum[CCH];
__device__ float g_bias2[BATCH*CCH];

// --------------------------- asm helpers -----------------------------------
__device__ __forceinline__ uint32_t smem_u32(const void* p) {
    uint32_t a;
    asm("{ .reg .u64 t; cvta.to.shared.u64 t, %1; cvt.u32.u64 %0, t; }" : "=r"(a) : "l"(p));
    return a;
}
__device__ __forceinline__ void cp16(uint32_t saddr, const void* g) {
    asm volatile("cp.async.cg.shared.global [%0], [%1], 16;" :: "r"(saddr), "l"(g) : "memory");
}
__device__ __forceinline__ void cp_commit() {
    asm volatile("cp.async.commit_group;" ::: "memory");
}
template<int N>
__device__ __forceinline__ void cp_wait() {
    asm volatile("cp.async.wait_group %0;" :: "n"(N) : "memory");
}
__device__ __forceinline__ void ldsm4(uint32_t* r, uint32_t a) {
    asm volatile("ldmatrix.sync.aligned.m8n8.x4.shared.b16 {%0,%1,%2,%3}, [%4];"
                 : "=r"(r[0]), "=r"(r[1]), "=r"(r[2]), "=r"(r[3]) : "r"(a));
}
__device__ __forceinline__ void mma16816(float* d, const uint32_t* a, const uint32_t* b) {
    asm volatile("mma.sync.aligned.m16n8k16.row.col.f32.f16.f16.f32 "
                 "{%0,%1,%2,%3}, {%4,%5,%6,%7}, {%8,%9}, {%0,%1,%2,%3};"
                 : "+f"(d[0]), "+f"(d[1]), "+f"(d[2]), "+f"(d[3])
                 : "r"(a[0]), "r"(a[1]), "r"(a[2]), "r"(a[3]), "r"(b[0]), "r"(b[1]));
}
__device__ __forceinline__ uint32_t pack2(__half a, __half b) {
    __half2 p; p.x = a; p.y = b;
    return *reinterpret_cast<uint32_t*>(&p);
}

// --------------------------- GEMM kernel -----------------------------------
// CTA tile 128x128, BK=32, 3-stage cp.async pipeline.
// SMEM tile: 128 rows x 32 halves, row padded to 80B.
// NMMA=1: tiles A,B.  NMMA=2: A-split (Ah, Al) + B.
// KSPLIT: blockIdx.z = b + 8*slice; slice covers K columns [slice*K, slice*K+K).
#define RSB   80
#define TILEB 10240

// EPI: 1 = f32 + e1[m]*e2[n]; 2 = gamma*(v+e1)+xres; 3 = half out; 4 = f32 plain.
template<int NMMA, int EPI, bool KSPLIT>
__global__ __launch_bounds__(256)
void gemm_f16(const __half* __restrict__ Ah, const __half* __restrict__ Al,
              const __half* __restrict__ Bh,
              int ldA, int ldB, long sA, long sB, int K,
              __half* __restrict__ Dh,
              float* __restrict__ Dout, int ldD, long sD,
              const float* __restrict__ e1, long se1,
              const float* __restrict__ e2,
              const float* __restrict__ xres,
              const float* __restrict__ gptr)
{
    constexpr int NTILES = (NMMA == 2) ? 3 : 2;
    constexpr int STGB   = NTILES * TILEB;
    constexpr int BOFF   = (NMMA == 2) ? 2 * TILEB : TILEB;

    extern __shared__ char sm[];
    const uint32_t sb = smem_u32(sm);
    const int tid = threadIdx.x, lane = tid & 31, wid = tid >> 5;
    const int wm = (wid >> 2) * 64, wn = (wid & 3) * 32;
    const int b      = KSPLIT ? (blockIdx.z & 7) : blockIdx.z;
    const int kslice = KSPLIT ? (blockIdx.z >> 3) : 0;
    const int m0 = blockIdx.y * 128, n0 = blockIdx.x * 128;

    Ah += b * sA + (long)kslice * K;
    if (NMMA == 2) Al += (long)kslice * K;
    Bh += b * sB + (long)kslice * K;
    if (KSPLIT) Dout += (long)kslice * BATCH * sD;

    const uint32_t aoff = ((lane & 7) + 8 * ((lane >> 3) & 1)) * RSB + (lane >> 4) * 16;
    const uint32_t boff = ((lane & 7) + 8 * (lane >> 4)) * RSB + ((lane >> 3) & 1) * 16;

    const int r0c = tid >> 2;
    const int c16 = tid & 3;

    float acc[4][4][4];
    #pragma unroll
    for (int i = 0; i < 4; i++)
        #pragma unroll
        for (int j = 0; j < 4; j++)
            #pragma unroll
            for (int v = 0; v < 4; v++) acc[i][j][v] = 0.f;

    const int nc = K >> 5;

    auto load_stage = [&](int stage, int k0) {
        uint32_t base = sb + stage * STGB;
        #pragma unroll
        for (int i = 0; i < 2; i++) {
            int row = r0c + i * 64;
            uint32_t so = base + row * RSB + c16 * 16;
            long ga = (long)(m0 + row) * ldA + k0 + c16 * 8;
            cp16(so, Ah + ga);
            if (NMMA == 2) cp16(so + TILEB, Al + ga);
            cp16(so + BOFF, Bh + (long)(n0 + row) * ldB + k0 + c16 * 8);
        }
    };

    auto compute_stage = [&](int stage) {
        uint32_t Abase = sb + stage * STGB;
        uint32_t Bbase = Abase + BOFF;
        #pragma unroll
        for (int ks = 0; ks < 2; ks++) {
            uint32_t kb2 = ks * 32;
            uint32_t ah[4][4], al[4][4], bh[4][2];
            #pragma unroll
            for (int mi = 0; mi < 4; mi++) {
                ldsm4(ah[mi], Abase + (wm + mi * 16) * RSB + kb2 + aoff);
                if (NMMA == 2) ldsm4(al[mi], Abase + TILEB + (wm + mi * 16) * RSB + kb2 + aoff);
            }
            #pragma unroll
            for (int nb = 0; nb < 2; nb++) {
                uint32_t t[4];
                ldsm4(t, Bbase + (wn + nb * 16) * RSB + kb2 + boff);
                bh[2*nb][0] = t[0]; bh[2*nb][1] = t[1];
                bh[2*nb+1][0] = t[2]; bh[2*nb+1][1] = t[3];
            }
            #pragma unroll
            for (int mi = 0; mi < 4; mi++)
                #pragma unroll
                for (int ni = 0; ni < 4; ni++) {
                    mma16816(acc[mi][ni], ah[mi], bh[ni]);
                    if (NMMA == 2) mma16816(acc[mi][ni], al[mi], bh[ni]);
                }
        }
    };

    load_stage(0, 0);
    cp_commit();
    if (nc > 1) load_stage(1, 32);
    cp_commit();
    for (int c = 0; c < nc; c++) {
        cp_wait<1>();
        __syncthreads();
        if (c + 2 < nc) load_stage((c + 2) % 3, (c + 2) * 32);
        cp_commit();
        compute_stage(c % 3);
    }

    // ------------------------------ epilogue -------------------------------
    float g = 0.f;
    if (EPI == 2) g = gptr[0];
    #pragma unroll
    for (int mi = 0; mi < 4; mi++) {
        #pragma unroll
        for (int half_ = 0; half_ < 2; half_++) {
            int r = m0 + wm + mi * 16 + (lane >> 2) + half_ * 8;
            float e1r = 0.f;
            if (EPI == 1) e1r = e1[r];
            if (EPI == 2) e1r = e1[b * se1 + r];
            #pragma unroll
            for (int ni = 0; ni < 4; ni++) {
                int cidx = n0 + wn + ni * 8 + 2 * (lane & 3);
                float v0 = acc[mi][ni][half_ * 2 + 0];
                float v1 = acc[mi][ni][half_ * 2 + 1];
                long idx = (long)r * ldD + cidx;
                if (EPI == 3) {
                    __half2 ph;
                    ph.x = __float2half_rn(v0); ph.y = __float2half_rn(v1);
                    *reinterpret_cast<__half2*>(Dh + b * sD + idx) = ph;
                } else if (EPI == 4) {
                    float2 o; o.x = v0; o.y = v1;
                    *reinterpret_cast<float2*>(Dout + b * sD + idx) = o;
                } else if (EPI == 1) {
                    float2 o;
                    o.x = v0 + e1r * e2[cidx];
                    o.y = v1 + e1r * e2[cidx + 1];
                    *reinterpret_cast<float2*>(Dout + b * sD + idx) = o;
                } else {
                    float2 xr = *reinterpret_cast<const float2*>(xres + b * sD + idx);
                    float2 o;
                    o.x = g * (v0 + e1r) + xr.x;
                    o.y = g * (v1 + e1r) + xr.y;
                    *reinterpret_cast<float2*>(Dout + b * sD + idx) = o;
                }
            }
        }
    }
}

// split-K reduction: Ph = half(p0 + p1)
__global__ __launch_bounds__(256)
void reduceP_kernel(const float4* __restrict__ p0, const float4* __restrict__ p1,
                    uint2* __restrict__ Ph)
{
    int i = blockIdx.x * 256 + threadIdx.x;
    float4 a = p0[i], c = p1[i];
    uint2 u;
    u.x = pack2(__float2half_rn(a.x + c.x), __float2half_rn(a.y + c.y));
    u.y = pack2(__float2half_rn(a.z + c.z), __float2half_rn(a.w + c.w));
    Ph[i] = u;
}

// ------------------------- prep kernels ------------------------------------
// x: convert to fp16 (CxN) and transposed fp16 (NxC). 64x64 tiles, vector I/O.
__global__ __launch_bounds__(256)
void xprep_kernel(const float* __restrict__ x,
                  __half* __restrict__ xh, __half* __restrict__ xTh)
{
    __shared__ __half t[64][66];
    const int b  = blockIdx.z;
    const int n0 = blockIdx.x * 64, c0 = blockIdx.y * 64;
    const int tx = threadIdx.x & 15, ty = threadIdx.x >> 4;
    const long sb_ = (long)b * CCH * NPIX;
    const float* xb = x + sb_;

    #pragma unroll
    for (int i = 0; i < 4; i++) {
        int cl = ty + 16 * i;
        float4 v = *reinterpret_cast<const float4*>(xb + (long)(c0 + cl) * NPIX + n0 + tx * 4);
        uint32_t p0 = pack2(__float2half_rn(v.x), __float2half_rn(v.y));
        uint32_t p1 = pack2(__float2half_rn(v.z), __float2half_rn(v.w));
        uint2 u; u.x = p0; u.y = p1;
        *reinterpret_cast<uint2*>(xh + sb_ + (long)(c0 + cl) * NPIX + n0 + tx * 4) = u;
        *reinterpret_cast<uint32_t*>(&t[cl][tx * 4])     = p0;
        *reinterpret_cast<uint32_t*>(&t[cl][tx * 4 + 2]) = p1;
    }
    __syncthreads();
    #pragma unroll
    for (int i = 0; i < 4; i++) {
        int nl = ty + 16 * i;
        uint2 u;
        u.x = pack2(t[tx*4+0][nl], t[tx*4+1][nl]);
        u.y = pack2(t[tx*4+2][nl], t[tx*4+3][nl]);
        *reinterpret_cast<uint2*>(xTh + sb_ + (long)(n0 + nl) * CCH + c0 + tx * 4) = u;
    }
}

// q: convert to fp16 + row sums (qsum). One block per d row.
__global__ __launch_bounds__(256)
void qprep_kernel(const float* __restrict__ q, __half* __restrict__ qh)
{
    const int d = blockIdx.x, tid = threadIdx.x;
    const float4* row = reinterpret_cast<const float4*>(q + (long)d * NPIX);
    uint2* orow = reinterpret_cast<uint2*>(qh + (long)d * NPIX);
    float s = 0.f;
    #pragma unroll
    for (int j = 0; j < 4; j++) {
        int i = tid + j * 256;
        float4 v = row[i];
        s += v.x + v.y + v.z + v.w;
        uint2 u;
        u.x = pack2(__float2half_rn(v.x), __float2half_rn(v.y));
        u.y = pack2(__float2half_rn(v.z), __float2half_rn(v.w));
        orow[i] = u;
    }
    #pragma unroll
    for (int o = 16; o; o >>= 1) s += __shfl_xor_sync(0xffffffffu, s, o);
    __shared__ float sh[8];
    if ((tid & 31) == 0) sh[tid >> 5] = s;
    __syncthreads();
    if (tid == 0) {
        float t = 0.f;
        #pragma unroll
        for (int i = 0; i < 8; i++) t += sh[i];
        g_qsum[d] = t;
    }
}

// kw hi/lo convert (blocks 0..255) + vw transpose->fp16 (blocks 256..511)
__global__ __launch_bounds__(256)
void wprep_kernel(const float* __restrict__ kw, const float* __restrict__ vw,
                  uint2* __restrict__ kwh, uint2* __restrict__ kwl,
                  __half* __restrict__ vwTh)
{
    __shared__ float smf[32][33];
    if (blockIdx.x < 256) {
        int i = blockIdx.x * 256 + threadIdx.x;
        float4 v = reinterpret_cast<const float4*>(kw)[i];
        float f[4] = {v.x, v.y, v.z, v.w};
        __half h[4], l[4];
        #pragma unroll
        for (int j = 0; j < 4; j++) {
            h[j] = __float2half_rn(f[j]);
            l[j] = __float2half_rn(f[j] - __half2float(h[j]));
        }
        uint2 uh, ul;
        uh.x = pack2(h[0], h[1]); uh.y = pack2(h[2], h[3]);
        ul.x = pack2(l[0], l[1]); ul.y = pack2(l[2], l[3]);
        kwh[i] = uh; kwl[i] = ul;
    } else {
        int t = blockIdx.x - 256;
        int x0 = (t & 15) * 32, y0 = (t >> 4) * 32;
        int tx = threadIdx.x & 31, ty = threadIdx.x >> 5;
        #pragma unroll
        for (int i = 0; i < 4; i++)
            smf[ty + i * 8][tx] = vw[(long)(y0 + ty + i * 8) * CCH + x0 + tx];
        __syncthreads();
        #pragma unroll
        for (int i = 0; i < 4; i++)
            vwTh[(long)(x0 + ty + i * 8) * CCH + y0 + tx] = __float2half_rn(smf[tx][ty + i * 8]);
    }
}

// fused softmax (rows of g_E) + transposed fp16 write to aTh
__global__ __launch_bounds__(256)
void smtrans_kernel(__half* __restrict__ aTh)
{
    __shared__ __half s[8][512];
    const int w = threadIdx.x >> 5, lane = threadIdx.x & 31;
    const long r = (long)blockIdx.x * 8 + w;
    const float* row = g_E + r * CCH;

    float v[16];
    float m = -1e30f;
    #pragma unroll
    for (int k = 0; k < 16; k++) { v[k] = row[lane + 32 * k]; m = fmaxf(m, v[k]); }
    #pragma unroll
    for (int o = 16; o; o >>= 1) m = fmaxf(m, __shfl_xor_sync(0xffffffffu, m, o));
    float ss = 0.f;
    #pragma unroll
    for (int k = 0; k < 16; k++) { v[k] = expf(v[k] - m); ss += v[k]; }
    #pragma unroll
    for (int o = 16; o; o >>= 1) ss += __shfl_xor_sync(0xffffffffu, ss, o);
    float inv = 1.f / ss;
    #pragma unroll
    for (int k = 0; k < 16; k++)
        s[w][lane + 32 * k] = __float2half_rn(v[k] * inv);
    __syncthreads();

    const int b  = (blockIdx.x * 8) >> 9;
    const int c0 = (blockIdx.x * 8) & 511;
    __half* out = aTh + (long)b * CCH * CCH + c0;
    #pragma unroll
    for (int dd = 0; dd < 2; dd++) {
        int d = 2 * threadIdx.x + dd;
        uint4 u;
        u.x = pack2(s[0][d], s[1][d]);
        u.y = pack2(s[2][d], s[3][d]);
        u.z = pack2(s[4][d], s[5][d]);
        u.w = pack2(s[6][d], s[7][d]);
        *reinterpret_cast<uint4*>(out + (long)d * CCH) = u;
    }
}

// bias2[b,c] = sum_d aTh[(b,c)][d]*vb[d]
__global__ __launch_bounds__(256)
void bias2_kernel(const __half* __restrict__ aTh, const float* __restrict__ vb)
{
    const int row = blockIdx.x * 8 + (threadIdx.x >> 5);
    const int lane = threadIdx.x & 31;
    const __half* ar = aTh + (long)row * CCH;
    float s = 0.f;
    #pragma unroll
    for (int k = 0; k < 16; k++) {
        int d = lane + 32 * k;
        s += __half2float(ar[d]) * vb[d];
    }
    #pragma unroll
    for (int o = 16; o; o >>= 1) s += __shfl_xor_sync(0xffffffffu, s, o);
    if (lane == 0) g_bias2[row] = s;
}

// ---------------------------------------------------------------------------
extern "C" void kernel_launch(void* const* d_in, const int* in_sizes, int n_in,
                              void* d_out, int out_size)
{
    const float* x     = (const float*)d_in[0];
    const float* q     = (const float*)d_in[1];
    const float* kw    = (const float*)d_in[2];
    const float* kb    = (const float*)d_in[3];
    const float* vw    = (const float*)d_in[4];
    const float* vb    = (const float*)d_in[5];
    const float* gamma = (const float*)d_in[6];
    float* out = (float*)d_out;

    const int SM1 = 3 * 2 * TILEB;   // 61440
    const int SM2 = 3 * 3 * TILEB;   // 92160
    cudaFuncSetAttribute((const void*)gemm_f16<1,4,true>,  cudaFuncAttributeMaxDynamicSharedMemorySize, SM1);
    cudaFuncSetAttribute((const void*)gemm_f16<1,2,false>, cudaFuncAttributeMaxDynamicSharedMemorySize, SM1);
    cudaFuncSetAttribute((const void*)gemm_f16<1,3,false>, cudaFuncAttributeMaxDynamicSharedMemorySize, SM1);
    cudaFuncSetAttribute((const void*)gemm_f16<2,1,false>, cudaFuncAttributeMaxDynamicSharedMemorySize, SM2);

    __half *xh, *xTh, *qh, *kwh, *kwl, *vwTh, *Ph, *aTh, *W2h;
    float *pE, *pq, *pb2, *pPp;
    cudaGetSymbolAddress((void**)&xh,  g_xh);
    cudaGetSymbolAddress((void**)&xTh, g_xTh);
    cudaGetSymbolAddress((void**)&qh,  g_qh);
    cudaGetSymbolAddress((void**)&kwh, g_kwh);
    cudaGetSymbolAddress((void**)&kwl, g_kwl);
    cudaGetSymbolAddress((void**)&vwTh,g_vwTh);
    cudaGetSymbolAddress((void**)&Ph,  g_Ph);
    cudaGetSymbolAddress((void**)&aTh, g_aTh);
    cudaGetSymbolAddress((void**)&W2h, g_W2h);
    cudaGetSymbolAddress((void**)&pPp, g_Pp);
    cudaGetSymbolAddress((void**)&pE,  g_E);
    cudaGetSymbolAddress((void**)&pq,  g_qsum);
    cudaGetSymbolAddress((void**)&pb2, g_bias2);

    const long sCC = (long)CCH * CCH;
    const long sCN = (long)CCH * NPIX;

    // ---- prep ----
    qprep_kernel<<<CCH, 256>>>(q, qh);
    xprep_kernel<<<dim3(NPIX/64, CCH/64, BATCH), 256>>>(x, xh, xTh);
    wprep_kernel<<<512, 256>>>(kw, vw, (uint2*)kwh, (uint2*)kwl, vwTh);

    // ---- GEMM1 (split-K=2): Pp[s][b][d][c] = sum_{n in slice s} q[d][n]*x[b][c][n] ----
    gemm_f16<1,4,true><<<dim3(4,4,16), 256, SM1>>>(
        qh, (const __half*)0, xh, NPIX, NPIX, 0, sCN, 2048,
        (__half*)0, pPp, CCH, sCC,
        (const float*)0, 0, (const float*)0, (const float*)0, (const float*)0);

    // ---- reduce: Ph = half(Pp[0] + Pp[1]) ----
    reduceP_kernel<<<(BATCH*CCH*CCH/4)/256, 256>>>(
        (const float4*)pPp, (const float4*)(pPp + BATCH*sCC), (uint2*)Ph);

    // ---- GEMM2: E[b][c][d] = sum_k kw[c][k]*P[b][d][k] + kb[c]*qsum[d] (kw split) ----
    gemm_f16<2,1,false><<<dim3(4,4,BATCH), 256, SM2>>>(
        kwh, kwl, Ph, CCH, CCH, 0, sCC, CCH,
        (__half*)0, pE, CCH, sCC,
        kb, 0, pq, (const float*)0, (const float*)0);

    // ---- fused softmax + transpose, then bias2 ----
    smtrans_kernel<<<BATCH*CCH/8, 256>>>(aTh);
    bias2_kernel<<<BATCH*CCH/8, 256>>>(aTh, vb);

    // ---- GEMM3: W2[b][c][o] = sum_d attT[c][d]*vwT[o][d] ----
    gemm_f16<1,3,false><<<dim3(4,4,BATCH), 256, SM1>>>(
        aTh, (const __half*)0, vwTh, CCH, CCH, sCC, 0, CCH,
        W2h, (float*)0, CCH, sCC,
        (const float*)0, 0, (const float*)0, (const float*)0, (const float*)0);

    // ---- GEMM4: out = gamma*(W2 @ xT + bias2) + x ----
    gemm_f16<1,2,false><<<dim3(NPIX/128, 4, BATCH), 256, SM1>>>(
        W2h, (const __half*)0, xTh, CCH, CCH, sCC, sCN, CCH,
        (__half*)0, out, NPIX, sCN,
        pb2, CCH, (const float*)0, x, gamma);
}